// round 1
// baseline (speedup 1.0000x reference)
#include <cuda_runtime.h>
#include <math.h>

#define NN 100000
#define NE 1600000
#define INF_ 128
#define HID 64
#define HEADS 4
#define NCLS 16
#define C1 256   // HEADS*HID
#define C2 64    // HEADS*NCLS
#define NCH 98   // ceil(NN/1024)

// ---------------- scratch (static device memory; no allocations) ----------------
__device__ __align__(16) float d_Wh1[(size_t)NN * C1];
__device__ __align__(16) float d_h1[(size_t)NN * C1];    // agg1 output, then ELU in place
__device__ __align__(16) float d_Wh2[(size_t)NN * C2];
__device__ __align__(16) float d_out2[(size_t)NN * C2];
__device__ __align__(16) float d_el1[NN * HEADS];
__device__ __align__(16) float d_er1[NN * HEADS];
__device__ __align__(16) float d_el2[NN * HEADS];
__device__ __align__(16) float d_er2[NN * HEADS];
__device__ int   d_deg[NN];
__device__ int   d_rowstart[NN];
__device__ int   d_cursor[NN];
__device__ int   d_csr[NE];
__device__ int   d_csum[128];
__device__ float d_cls[NCLS];

// ---------------- small helpers ----------------
__device__ __forceinline__ float4 f4make(float v) { return make_float4(v, v, v, v); }
__device__ __forceinline__ float4 f4add(float4 a, float4 b) {
    return make_float4(a.x + b.x, a.y + b.y, a.z + b.z, a.w + b.w);
}
__device__ __forceinline__ float4 f4leaky(float4 a) {
    return make_float4(fmaxf(a.x, 0.2f * a.x), fmaxf(a.y, 0.2f * a.y),
                       fmaxf(a.z, 0.2f * a.z), fmaxf(a.w, 0.2f * a.w));
}
__device__ __forceinline__ float4 f4max(float4 a, float4 b) {
    return make_float4(fmaxf(a.x, b.x), fmaxf(a.y, b.y), fmaxf(a.z, b.z), fmaxf(a.w, b.w));
}
__device__ __forceinline__ float4 f4expsub(float4 e, float4 m) {
    return make_float4(__expf(e.x - m.x), __expf(e.y - m.y),
                       __expf(e.z - m.z), __expf(e.w - m.w));
}
__device__ __forceinline__ float pick4(float4 v, int h) {
    float r = v.x;
    if (h == 1) r = v.y;
    if (h == 2) r = v.z;
    if (h == 3) r = v.w;
    return r;
}

// ---------------- init ----------------
__global__ void k_init() {
    int i = blockIdx.x * blockDim.x + threadIdx.x;
    if (i < NN) d_deg[i] = 0;
    if (i < NCLS) d_cls[i] = 0.f;
}

// ---------------- CSR build ----------------
__global__ void k_hist(const int* __restrict__ dst) {
    int e = blockIdx.x * blockDim.x + threadIdx.x;
    if (e < NE) atomicAdd(&d_deg[dst[e]], 1);
}

__global__ void k_chunkred() {
    int c = blockIdx.x, base = c * 1024;
    int s = 0;
    for (int i = threadIdx.x; i < 1024; i += 256) {
        int idx = base + i;
        if (idx < NN) s += d_deg[idx];
    }
    for (int o = 16; o; o >>= 1) s += __shfl_xor_sync(0xffffffffu, s, o);
    __shared__ int ws[8];
    if ((threadIdx.x & 31) == 0) ws[threadIdx.x >> 5] = s;
    __syncthreads();
    if (threadIdx.x == 0) {
        int t = 0;
        for (int i = 0; i < 8; i++) t += ws[i];
        d_csum[c] = t;
    }
}

__global__ void k_scantop() {
    int acc = 0;
    for (int c = 0; c < NCH; c++) {
        int t = d_csum[c];
        d_csum[c] = acc;
        acc += t;
    }
}

__global__ void k_scanlocal() {
    int c = blockIdx.x, base = c * 1024, tid = threadIdx.x;
    int v[4];
    int i0 = base + tid * 4;
#pragma unroll
    for (int j = 0; j < 4; j++) v[j] = (i0 + j < NN) ? d_deg[i0 + j] : 0;
    int ts = v[0] + v[1] + v[2] + v[3];
    int lane = tid & 31, wp = tid >> 5;
    int x = ts;
#pragma unroll
    for (int o = 1; o < 32; o <<= 1) {
        int y = __shfl_up_sync(0xffffffffu, x, o);
        if (lane >= o) x += y;
    }
    __shared__ int ws[8], wo[8];
    if (lane == 31) ws[wp] = x;
    __syncthreads();
    if (tid == 0) {
        int a = 0;
        for (int k = 0; k < 8; k++) { wo[k] = a; a += ws[k]; }
    }
    __syncthreads();
    int run = d_csum[c] + wo[wp] + (x - ts);
#pragma unroll
    for (int j = 0; j < 4; j++) {
        if (i0 + j < NN) {
            d_rowstart[i0 + j] = run;
            d_cursor[i0 + j] = run;
            run += v[j];
        }
    }
}

__global__ void k_scatter(const int* __restrict__ src, const int* __restrict__ dst) {
    int e = blockIdx.x * blockDim.x + threadIdx.x;
    if (e < NE) {
        int d = dst[e];
        int p = atomicAdd(&d_cursor[d], 1);
        d_csr[p] = src[e];
    }
}

// ---------------- GEMM1: Wh1[n, h*64+o] = h[n,:] @ W1[h,:,o] + b1[h,o] ----------------
__global__ __launch_bounds__(256) void k_gemm1(const float* __restrict__ H,
                                               const float* __restrict__ W1,
                                               const float* __restrict__ B1) {
    __shared__ float As[INF_][64];   // [k][m]
    __shared__ float Bs[INF_][HID];  // [k][o]
    int m0 = blockIdx.x * 64, hd = blockIdx.y, tid = threadIdx.x;
    {   // stage A transposed (lanes over m -> conflict-free STS)
        int m = tid & 63, kq = tid >> 6;
        int gm = m0 + m;
        bool ok = gm < NN;
        const float4* hp = (const float4*)(H + (size_t)gm * INF_);
#pragma unroll
        for (int ll = 0; ll < 8; ll++) {
            int k4 = kq + ll * 4;
            float4 v = ok ? hp[k4] : make_float4(0, 0, 0, 0);
            As[k4 * 4 + 0][m] = v.x;
            As[k4 * 4 + 1][m] = v.y;
            As[k4 * 4 + 2][m] = v.z;
            As[k4 * 4 + 3][m] = v.w;
        }
    }
    {   // stage B
        int o4 = tid & 15, k0 = tid >> 4;
        const float* Bg = W1 + (size_t)hd * INF_ * HID;
#pragma unroll
        for (int kk = 0; kk < 8; kk++) {
            int k = k0 + kk * 16;
            *(float4*)&Bs[k][o4 * 4] = *(const float4*)(Bg + k * HID + o4 * 4);
        }
    }
    __syncthreads();
    int tx = tid & 15, ty = tid >> 4;
    float acc[4][4] = {};
#pragma unroll 16
    for (int k = 0; k < INF_; k++) {
        float4 a = *(const float4*)&As[k][ty * 4];
        float4 b = *(const float4*)&Bs[k][tx * 4];
        float av[4] = {a.x, a.y, a.z, a.w};
        float bv[4] = {b.x, b.y, b.z, b.w};
#pragma unroll
        for (int i = 0; i < 4; i++)
#pragma unroll
            for (int j = 0; j < 4; j++) acc[i][j] = fmaf(av[i], bv[j], acc[i][j]);
    }
    float4 bias = *(const float4*)(B1 + hd * HID + tx * 4);
    float bb[4] = {bias.x, bias.y, bias.z, bias.w};
#pragma unroll
    for (int i = 0; i < 4; i++) {
        int gm = m0 + ty * 4 + i;
        if (gm < NN) {
            float4 o = make_float4(acc[i][0] + bb[0], acc[i][1] + bb[1],
                                   acc[i][2] + bb[2], acc[i][3] + bb[3]);
            *(float4*)&d_Wh1[(size_t)gm * C1 + hd * HID + tx * 4] = o;
        }
    }
}

// ---------------- per-node attention scalars, layer 1 ----------------
__global__ void k_elr1(const float* __restrict__ a1) {
    int tid = threadIdx.x;
    int h = tid >> 6, o = tid & 63;
    float ad = a1[h * 128 + o];        // a[:, :O] (dst side)
    float as = a1[h * 128 + 64 + o];   // a[:, O:] (src side)
    int lane = tid & 31, wp = tid >> 5;
    __shared__ float sel[8], ser[8];
    for (int nn = 0; nn < 8; nn++) {
        int n = blockIdx.x * 8 + nn;
        if (n >= NN) break;
        float v = d_Wh1[(size_t)n * C1 + tid];
        float pl = v * ad, pr = v * as;
#pragma unroll
        for (int off = 16; off; off >>= 1) {
            pl += __shfl_xor_sync(0xffffffffu, pl, off);
            pr += __shfl_xor_sync(0xffffffffu, pr, off);
        }
        if (lane == 0) { sel[wp] = pl; ser[wp] = pr; }
        __syncthreads();
        if (tid < HEADS) {
            d_el1[n * 4 + tid] = sel[2 * tid] + sel[2 * tid + 1];
            d_er1[n * 4 + tid] = ser[2 * tid] + ser[2 * tid + 1];
        }
        __syncthreads();
    }
}

// ---------------- layer-1 segment softmax + aggregation (warp per dst node) ------
__global__ __launch_bounds__(256) void k_agg1(const float* __restrict__ ab1) {
    int w = (blockIdx.x * blockDim.x + threadIdx.x) >> 5;
    int lane = threadIdx.x & 31;
    if (w >= NN) return;
    int n = w;
    int start = d_rowstart[n], deg = d_deg[n];
    float4* outp = (float4*)(d_h1 + (size_t)n * C1);
    if (deg == 0) {
        float4 z = make_float4(0, 0, 0, 0);
        outp[lane] = z;
        outp[32 + lane] = z;
        return;
    }
    float4 el = *(const float4*)(d_el1 + n * 4);
    float4 ab = make_float4(ab1[0], ab1[1], ab1[2], ab1[3]);
    float4 elb = f4add(el, ab);
    // phase 1: max
    float4 mx = f4make(-INFINITY);
    for (int i = lane; i < deg; i += 32) {
        int s = d_csr[start + i];
        float4 er = *(const float4*)(d_er1 + s * 4);
        mx = f4max(mx, f4leaky(f4add(elb, er)));
    }
#pragma unroll
    for (int off = 16; off; off >>= 1) {
        mx.x = fmaxf(mx.x, __shfl_xor_sync(0xffffffffu, mx.x, off));
        mx.y = fmaxf(mx.y, __shfl_xor_sync(0xffffffffu, mx.y, off));
        mx.z = fmaxf(mx.z, __shfl_xor_sync(0xffffffffu, mx.z, off));
        mx.w = fmaxf(mx.w, __shfl_xor_sync(0xffffffffu, mx.w, off));
    }
    // phase 2: sum of exp
    float4 se = f4make(0.f);
    for (int i = lane; i < deg; i += 32) {
        int s = d_csr[start + i];
        float4 er = *(const float4*)(d_er1 + s * 4);
        float4 e = f4leaky(f4add(elb, er));
        se = f4add(se, f4expsub(e, mx));
    }
#pragma unroll
    for (int off = 16; off; off >>= 1) {
        se.x += __shfl_xor_sync(0xffffffffu, se.x, off);
        se.y += __shfl_xor_sync(0xffffffffu, se.y, off);
        se.z += __shfl_xor_sync(0xffffffffu, se.z, off);
        se.w += __shfl_xor_sync(0xffffffffu, se.w, off);
    }
    float4 inv = make_float4(1.f / se.x, 1.f / se.y, 1.f / se.z, 1.f / se.w);
    // phase 3: weighted aggregate; lane owns float4 cols q=lane and q=32+lane
    int hsel = (lane & 16) ? 1 : 0;
    float m0v = hsel ? mx.y : mx.x;
    float m1v = hsel ? mx.w : mx.z;
    float i0v = hsel ? inv.y : inv.x;
    float i1v = hsel ? inv.w : inv.z;
    float eb0 = hsel ? elb.y : elb.x;
    float eb1 = hsel ? elb.w : elb.z;
    float4 acc0 = f4make(0.f), acc1 = f4make(0.f);
    const float4* wh = (const float4*)d_Wh1;
    for (int i = 0; i < deg; i++) {
        int s = d_csr[start + i];
        float4 er = *(const float4*)(d_er1 + s * 4);
        float er0 = hsel ? er.y : er.x;
        float er1 = hsel ? er.w : er.z;
        float e0 = eb0 + er0; e0 = fmaxf(e0, 0.2f * e0);
        float e1 = eb1 + er1; e1 = fmaxf(e1, 0.2f * e1);
        float al0 = __expf(e0 - m0v) * i0v;
        float al1 = __expf(e1 - m1v) * i1v;
        float4 w0 = wh[(size_t)s * 64 + lane];
        float4 w1 = wh[(size_t)s * 64 + 32 + lane];
        acc0.x = fmaf(al0, w0.x, acc0.x); acc0.y = fmaf(al0, w0.y, acc0.y);
        acc0.z = fmaf(al0, w0.z, acc0.z); acc0.w = fmaf(al0, w0.w, acc0.w);
        acc1.x = fmaf(al1, w1.x, acc1.x); acc1.y = fmaf(al1, w1.y, acc1.y);
        acc1.z = fmaf(al1, w1.z, acc1.z); acc1.w = fmaf(al1, w1.w, acc1.w);
    }
    outp[lane] = acc0;
    outp[32 + lane] = acc1;
}

// ---------------- ELU in place on h1 ----------------
__global__ void k_elu() {
    size_t i = (size_t)blockIdx.x * blockDim.x + threadIdx.x;
    size_t tot = (size_t)NN * C1 / 4;
    if (i < tot) {
        float4* p = (float4*)d_h1;
        float4 v = p[i];
        v.x = v.x > 0.f ? v.x : expm1f(v.x);
        v.y = v.y > 0.f ? v.y : expm1f(v.y);
        v.z = v.z > 0.f ? v.z : expm1f(v.z);
        v.w = v.w > 0.f ? v.w : expm1f(v.w);
        p[i] = v;
    }
}

// ---------------- GEMM2: Wh2[n, h*16+o] = h1[n,:] @ W2[h,:,o] + b2[h,o] ----------
__global__ __launch_bounds__(256) void k_gemm2(const float* __restrict__ W2,
                                               const float* __restrict__ B2) {
    __shared__ float As[128][64];
    __shared__ float Bs[128][C2];
    int m0 = blockIdx.x * 64, tid = threadIdx.x;
    int tx = tid & 15, ty = tid >> 4;
    float acc[4][4] = {};
    for (int kc = 0; kc < 256; kc += 128) {
        {
            int m = tid & 63, kq = tid >> 6;
            int gm = m0 + m;
            bool ok = gm < NN;
            const float4* hp = (const float4*)(d_h1 + (size_t)gm * C1 + kc);
#pragma unroll
            for (int ll = 0; ll < 8; ll++) {
                int k4 = kq + ll * 4;
                float4 v = ok ? hp[k4] : make_float4(0, 0, 0, 0);
                As[k4 * 4 + 0][m] = v.x;
                As[k4 * 4 + 1][m] = v.y;
                As[k4 * 4 + 2][m] = v.z;
                As[k4 * 4 + 3][m] = v.w;
            }
        }
        {
            int o4 = tid & 15, k0 = tid >> 4;
            int c0 = o4 * 4;
            int hh = c0 >> 4, oo = c0 & 15;
#pragma unroll
            for (int kk = 0; kk < 8; kk++) {
                int k = k0 + kk * 16;
                *(float4*)&Bs[k][c0] =
                    *(const float4*)(W2 + (size_t)hh * 256 * 16 + (size_t)(kc + k) * 16 + oo);
            }
        }
        __syncthreads();
#pragma unroll 16
        for (int k = 0; k < 128; k++) {
            float4 a = *(const float4*)&As[k][ty * 4];
            float4 b = *(const float4*)&Bs[k][tx * 4];
            float av[4] = {a.x, a.y, a.z, a.w};
            float bv[4] = {b.x, b.y, b.z, b.w};
#pragma unroll
            for (int i = 0; i < 4; i++)
#pragma unroll
                for (int j = 0; j < 4; j++) acc[i][j] = fmaf(av[i], bv[j], acc[i][j]);
        }
        __syncthreads();
    }
    int c0 = tx * 4;
    float4 bias = *(const float4*)(B2 + c0);  // b2 flattened [4*16] matches c=h*16+o
    float bb[4] = {bias.x, bias.y, bias.z, bias.w};
#pragma unroll
    for (int i = 0; i < 4; i++) {
        int gm = m0 + ty * 4 + i;
        if (gm < NN) {
            float4 o = make_float4(acc[i][0] + bb[0], acc[i][1] + bb[1],
                                   acc[i][2] + bb[2], acc[i][3] + bb[3]);
            *(float4*)&d_Wh2[(size_t)gm * C2 + c0] = o;
        }
    }
}

// ---------------- per-node attention scalars, layer 2 ----------------
__global__ void k_elr2(const float* __restrict__ a2) {
    int tid = threadIdx.x;
    int sub = tid >> 6, t = tid & 63, h = t >> 4, o = t & 15;
    int n = blockIdx.x * 4 + sub;
    if (n >= NN) return;
    float v = d_Wh2[(size_t)n * C2 + t];
    float pl = v * a2[h * 32 + o];
    float pr = v * a2[h * 32 + 16 + o];
#pragma unroll
    for (int off = 8; off; off >>= 1) {
        pl += __shfl_xor_sync(0xffffffffu, pl, off);
        pr += __shfl_xor_sync(0xffffffffu, pr, off);
    }
    if ((t & 15) == 0) {
        d_el2[n * 4 + h] = pl;
        d_er2[n * 4 + h] = pr;
    }
}

// ---------------- layer-2 segment softmax + aggregation ----------------
__global__ __launch_bounds__(256) void k_agg2(const float* __restrict__ ab2) {
    int w = (blockIdx.x * blockDim.x + threadIdx.x) >> 5;
    int lane = threadIdx.x & 31;
    if (w >= NN) return;
    int n = w;
    int start = d_rowstart[n], deg = d_deg[n];
    float2* outp = (float2*)(d_out2 + (size_t)n * C2);
    if (deg == 0) {
        outp[lane] = make_float2(0.f, 0.f);
        return;
    }
    float4 el = *(const float4*)(d_el2 + n * 4);
    float4 ab = make_float4(ab2[0], ab2[1], ab2[2], ab2[3]);
    float4 elb = f4add(el, ab);
    float4 mx = f4make(-INFINITY);
    for (int i = lane; i < deg; i += 32) {
        int s = d_csr[start + i];
        float4 er = *(const float4*)(d_er2 + s * 4);
        mx = f4max(mx, f4leaky(f4add(elb, er)));
    }
#pragma unroll
    for (int off = 16; off; off >>= 1) {
        mx.x = fmaxf(mx.x, __shfl_xor_sync(0xffffffffu, mx.x, off));
        mx.y = fmaxf(mx.y, __shfl_xor_sync(0xffffffffu, mx.y, off));
        mx.z = fmaxf(mx.z, __shfl_xor_sync(0xffffffffu, mx.z, off));
        mx.w = fmaxf(mx.w, __shfl_xor_sync(0xffffffffu, mx.w, off));
    }
    float4 se = f4make(0.f);
    for (int i = lane; i < deg; i += 32) {
        int s = d_csr[start + i];
        float4 er = *(const float4*)(d_er2 + s * 4);
        float4 e = f4leaky(f4add(elb, er));
        se = f4add(se, f4expsub(e, mx));
    }
#pragma unroll
    for (int off = 16; off; off >>= 1) {
        se.x += __shfl_xor_sync(0xffffffffu, se.x, off);
        se.y += __shfl_xor_sync(0xffffffffu, se.y, off);
        se.z += __shfl_xor_sync(0xffffffffu, se.z, off);
        se.w += __shfl_xor_sync(0xffffffffu, se.w, off);
    }
    // lane owns cols [2*lane, 2*lane+1]; head = lane/8
    int h = lane >> 3;
    float mh = pick4(mx, h);
    float ih = 1.f / pick4(se, h);
    float ebh = pick4(elb, h);
    float2 acc = make_float2(0.f, 0.f);
    const float2* wh = (const float2*)d_Wh2;
    for (int i = 0; i < deg; i++) {
        int s = d_csr[start + i];
        float4 er = *(const float4*)(d_er2 + s * 4);
        float e = ebh + pick4(er, h);
        e = fmaxf(e, 0.2f * e);
        float al = __expf(e - mh) * ih;
        float2 wv = wh[(size_t)s * 32 + lane];
        acc.x = fmaf(al, wv.x, acc.x);
        acc.y = fmaf(al, wv.y, acc.y);
    }
    outp[lane] = acc;
}

// ---------------- readout: head-mean -> softmax -> node-mean ----------------
__global__ void k_final() {
    __shared__ float ssum[NCLS];
    if (threadIdx.x < NCLS) ssum[threadIdx.x] = 0.f;
    __syncthreads();
    float loc[NCLS];
#pragma unroll
    for (int k = 0; k < NCLS; k++) loc[k] = 0.f;
    for (int n = blockIdx.x * blockDim.x + threadIdx.x; n < NN;
         n += gridDim.x * blockDim.x) {
        const float* row = d_out2 + (size_t)n * C2;
        float z[NCLS];
#pragma unroll
        for (int k = 0; k < NCLS; k++)
            z[k] = 0.25f * (row[k] + row[16 + k] + row[32 + k] + row[48 + k]);
        float mx = z[0];
#pragma unroll
        for (int k = 1; k < NCLS; k++) mx = fmaxf(mx, z[k]);
        float s = 0.f;
#pragma unroll
        for (int k = 0; k < NCLS; k++) {
            z[k] = __expf(z[k] - mx);
            s += z[k];
        }
        float invs = 1.f / s;
#pragma unroll
        for (int k = 0; k < NCLS; k++) loc[k] += z[k] * invs;
    }
#pragma unroll
    for (int k = 0; k < NCLS; k++) atomicAdd(&ssum[k], loc[k]);
    __syncthreads();
    if (threadIdx.x < NCLS) atomicAdd(&d_cls[threadIdx.x], ssum[threadIdx.x]);
}

__global__ void k_fc(const float* __restrict__ fcw, const float* __restrict__ fcb,
                     float* __restrict__ out) {
    int c = threadIdx.x;
    if (c < NCLS) {
        float s = fcb[c];
        const float scale = 1.f / (float)NN;
#pragma unroll
        for (int k = 0; k < NCLS; k++) s = fmaf(d_cls[k] * scale, fcw[c * NCLS + k], s);
        out[c] = s;
    }
}

// ---------------- launch ----------------
extern "C" void kernel_launch(void* const* d_in, const int* in_sizes, int n_in,
                              void* d_out, int out_size) {
    const float* h   = (const float*)d_in[0];
    const int*   src = (const int*)d_in[1];
    const int*   dst = (const int*)d_in[2];
    const float* W1  = (const float*)d_in[3];
    const float* b1  = (const float*)d_in[4];
    const float* a1  = (const float*)d_in[5];
    const float* ab1 = (const float*)d_in[6];
    const float* W2  = (const float*)d_in[7];
    const float* b2  = (const float*)d_in[8];
    const float* a2  = (const float*)d_in[9];
    const float* ab2 = (const float*)d_in[10];
    const float* fcw = (const float*)d_in[11];
    const float* fcb = (const float*)d_in[12];
    float* out = (float*)d_out;

    k_init<<<(NN + 255) / 256, 256>>>();
    k_hist<<<(NE + 255) / 256, 256>>>(dst);
    k_chunkred<<<NCH, 256>>>();
    k_scantop<<<1, 1>>>();
    k_scanlocal<<<NCH, 256>>>();
    k_scatter<<<(NE + 255) / 256, 256>>>(src, dst);

    k_gemm1<<<dim3((NN + 63) / 64, HEADS), 256>>>(h, W1, b1);
    k_elr1<<<(NN + 7) / 8, 256>>>(a1);
    k_agg1<<<(NN * 32 + 255) / 256, 256>>>(ab1);
    k_elu<<<(int)(((size_t)NN * C1 / 4 + 255) / 256), 256>>>();

    k_gemm2<<<(NN + 63) / 64, 256>>>(W2, b2);
    k_elr2<<<(NN + 3) / 4, 256>>>(a2);
    k_agg2<<<(NN * 32 + 255) / 256, 256>>>(ab2);

    k_final<<<400, 256>>>();
    k_fc<<<1, 32>>>(fcw, fcb, out);
}

// round 5
// speedup vs baseline: 1.2199x; 1.2199x over previous
#include <cuda_runtime.h>
#include <cuda_bf16.h>
#include <math.h>

#define NN 100000
#define NE 1600000
#define INF_ 128
#define HID 64
#define HEADS 4
#define NCLS 16
#define C1 256   // HEADS*HID
#define C2 64    // HEADS*NCLS
#define NCH 98   // ceil(NN/1024)

// ---------------- scratch (static device memory; no allocations) ----------------
__device__ __align__(16) __nv_bfloat16 d_Wh1b[(size_t)NN * C1];
__device__ __align__(16) float d_h1[(size_t)NN * C1];    // ELU(agg1)
__device__ __align__(16) __nv_bfloat16 d_Wh2b[(size_t)NN * C2];
__device__ __align__(16) float d_out2[(size_t)NN * C2];
__device__ __align__(16) float d_el1[NN * HEADS];
__device__ __align__(16) float d_er1[NN * HEADS];
__device__ __align__(16) float d_el2[NN * HEADS];
__device__ __align__(16) float d_er2[NN * HEADS];
__device__ int   d_deg[NN];
__device__ int   d_rowstart[NN];
__device__ int   d_cursor[NN];
__device__ int   d_csr[NE];
__device__ int   d_csum[128];
__device__ float d_cls[NCLS];

// ---------------- small helpers ----------------
__device__ __forceinline__ float4 f4make(float v) { return make_float4(v, v, v, v); }
__device__ __forceinline__ float4 f4add(float4 a, float4 b) {
    return make_float4(a.x + b.x, a.y + b.y, a.z + b.z, a.w + b.w);
}
__device__ __forceinline__ float4 f4leaky(float4 a) {
    return make_float4(fmaxf(a.x, 0.2f * a.x), fmaxf(a.y, 0.2f * a.y),
                       fmaxf(a.z, 0.2f * a.z), fmaxf(a.w, 0.2f * a.w));
}
__device__ __forceinline__ float4 f4max(float4 a, float4 b) {
    return make_float4(fmaxf(a.x, b.x), fmaxf(a.y, b.y), fmaxf(a.z, b.z), fmaxf(a.w, b.w));
}
__device__ __forceinline__ float4 f4expsub(float4 e, float4 m) {
    return make_float4(__expf(e.x - m.x), __expf(e.y - m.y),
                       __expf(e.z - m.z), __expf(e.w - m.w));
}
__device__ __forceinline__ float pick4(float4 v, int h) {
    float r = v.x;
    if (h == 1) r = v.y;
    if (h == 2) r = v.z;
    if (h == 3) r = v.w;
    return r;
}
__device__ __forceinline__ unsigned pack_bf2(float a, float b) {
    __nv_bfloat162 t = __floats2bfloat162_rn(a, b);
    return *reinterpret_cast<unsigned*>(&t);
}
__device__ __forceinline__ float eluf(float x) { return x > 0.f ? x : expm1f(x); }

// ---------------- init ----------------
__global__ void k_init() {
    int i = blockIdx.x * blockDim.x + threadIdx.x;
    if (i < NN) d_deg[i] = 0;
    if (i < NCLS) d_cls[i] = 0.f;
}

// ---------------- CSR build ----------------
__global__ void k_hist(const int* __restrict__ dst) {
    int e = blockIdx.x * blockDim.x + threadIdx.x;
    if (e < NE) atomicAdd(&d_deg[dst[e]], 1);
}

__global__ void k_chunkred() {   // d_csum[c] = total degree of chunk c
    int c = blockIdx.x, base = c * 1024;
    int s = 0;
    for (int i = threadIdx.x; i < 1024; i += 256) {
        int idx = base + i;
        if (idx < NN) s += d_deg[idx];
    }
    for (int o = 16; o; o >>= 1) s += __shfl_xor_sync(0xffffffffu, s, o);
    __shared__ int ws[8];
    if ((threadIdx.x & 31) == 0) ws[threadIdx.x >> 5] = s;
    __syncthreads();
    if (threadIdx.x == 0) {
        int t = 0;
        for (int i = 0; i < 8; i++) t += ws[i];
        d_csum[c] = t;
    }
}

__global__ void k_scanlocal() {
    int c = blockIdx.x, base = c * 1024, tid = threadIdx.x;
    // chunk-exclusive offset: sum of chunk totals before c
    __shared__ int s_off;
    {
        int part = 0;
        for (int t = tid; t < c; t += 256) part += d_csum[t];
        for (int o = 16; o; o >>= 1) part += __shfl_xor_sync(0xffffffffu, part, o);
        __shared__ int wsum[8];
        if ((tid & 31) == 0) wsum[tid >> 5] = part;
        __syncthreads();
        if (tid == 0) {
            int a = 0;
            for (int k = 0; k < 8; k++) a += wsum[k];
            s_off = a;
        }
        __syncthreads();
    }
    int v[4];
    int i0 = base + tid * 4;
#pragma unroll
    for (int j = 0; j < 4; j++) v[j] = (i0 + j < NN) ? d_deg[i0 + j] : 0;
    int ts = v[0] + v[1] + v[2] + v[3];
    int lane = tid & 31, wp = tid >> 5;
    int x = ts;
#pragma unroll
    for (int o = 1; o < 32; o <<= 1) {
        int y = __shfl_up_sync(0xffffffffu, x, o);
        if (lane >= o) x += y;
    }
    __shared__ int ws[8], wo[8];
    if (lane == 31) ws[wp] = x;
    __syncthreads();
    if (tid == 0) {
        int a = 0;
        for (int k = 0; k < 8; k++) { wo[k] = a; a += ws[k]; }
    }
    __syncthreads();
    int run = s_off + wo[wp] + (x - ts);
#pragma unroll
    for (int j = 0; j < 4; j++) {
        if (i0 + j < NN) {
            d_rowstart[i0 + j] = run;
            d_cursor[i0 + j] = run;
            run += v[j];
        }
    }
}

__global__ void k_scatter(const int* __restrict__ src, const int* __restrict__ dst) {
    int e = blockIdx.x * blockDim.x + threadIdx.x;
    if (e < NE) {
        int d = dst[e];
        int p = atomicAdd(&d_cursor[d], 1);
        d_csr[p] = src[e];
    }
}

// ---- GEMM1: Wh1[n, hd*64+o] = h[n,:]@W1[hd,:,o]+b1 ; epilogue: bf16 store + el/er ----
__global__ __launch_bounds__(256) void k_gemm1(const float* __restrict__ H,
                                               const float* __restrict__ W1,
                                               const float* __restrict__ B1,
                                               const float* __restrict__ A1) {
    __shared__ float As[INF_][64];   // [k][m]
    __shared__ float Bs[INF_][HID];  // [k][o]
    __shared__ float sEl[64][16];
    __shared__ float sEr[64][16];
    int m0 = blockIdx.x * 64, hd = blockIdx.y, tid = threadIdx.x;
    {   // stage A transposed
        int m = tid & 63, kq = tid >> 6;
        int gm = m0 + m;
        bool ok = gm < NN;
        const float4* hp = (const float4*)(H + (size_t)gm * INF_);
#pragma unroll
        for (int ll = 0; ll < 8; ll++) {
            int k4 = kq + ll * 4;
            float4 v = ok ? hp[k4] : make_float4(0, 0, 0, 0);
            As[k4 * 4 + 0][m] = v.x;
            As[k4 * 4 + 1][m] = v.y;
            As[k4 * 4 + 2][m] = v.z;
            As[k4 * 4 + 3][m] = v.w;
        }
    }
    {   // stage B
        int o4 = tid & 15, k0 = tid >> 4;
        const float* Bg = W1 + (size_t)hd * INF_ * HID;
#pragma unroll
        for (int kk = 0; kk < 8; kk++) {
            int k = k0 + kk * 16;
            *(float4*)&Bs[k][o4 * 4] = *(const float4*)(Bg + k * HID + o4 * 4);
        }
    }
    __syncthreads();
    int tx = tid & 15, ty = tid >> 4;
    float acc[4][4] = {};
#pragma unroll 16
    for (int k = 0; k < INF_; k++) {
        float4 a = *(const float4*)&As[k][ty * 4];
        float4 b = *(const float4*)&Bs[k][tx * 4];
        float av[4] = {a.x, a.y, a.z, a.w};
        float bv[4] = {b.x, b.y, b.z, b.w};
#pragma unroll
        for (int i = 0; i < 4; i++)
#pragma unroll
            for (int j = 0; j < 4; j++) acc[i][j] = fmaf(av[i], bv[j], acc[i][j]);
    }
    float4 bias = *(const float4*)(B1 + hd * HID + tx * 4);
    float bb[4] = {bias.x, bias.y, bias.z, bias.w};
    float4 a1d = *(const float4*)(A1 + hd * 128 + tx * 4);        // dst side
    float4 a1s = *(const float4*)(A1 + hd * 128 + 64 + tx * 4);   // src side
    float ad[4] = {a1d.x, a1d.y, a1d.z, a1d.w};
    float asr[4] = {a1s.x, a1s.y, a1s.z, a1s.w};
#pragma unroll
    for (int i = 0; i < 4; i++) {
        int gm = m0 + ty * 4 + i;
        float o0 = acc[i][0] + bb[0], o1 = acc[i][1] + bb[1];
        float o2 = acc[i][2] + bb[2], o3 = acc[i][3] + bb[3];
        sEl[ty * 4 + i][tx] = o0 * ad[0] + o1 * ad[1] + o2 * ad[2] + o3 * ad[3];
        sEr[ty * 4 + i][tx] = o0 * asr[0] + o1 * asr[1] + o2 * asr[2] + o3 * asr[3];
        if (gm < NN) {
            uint2 pk = make_uint2(pack_bf2(o0, o1), pack_bf2(o2, o3));
            *(uint2*)&d_Wh1b[(size_t)gm * C1 + hd * HID + tx * 4] = pk;
        }
    }
    __syncthreads();
    if (tid < 64) {
        int gm = m0 + tid;
        if (gm < NN) {
            float el = 0.f, er = 0.f;
#pragma unroll
            for (int t = 0; t < 16; t++) { el += sEl[tid][t]; er += sEr[tid][t]; }
            d_el1[gm * 4 + hd] = el;
            d_er1[gm * 4 + hd] = er;
        }
    }
}

// ---------------- layer-1 segment softmax + aggregation (warp per dst node) ------
__global__ __launch_bounds__(256) void k_agg1(const float* __restrict__ ab1) {
    int w = (blockIdx.x * blockDim.x + threadIdx.x) >> 5;
    int lane = threadIdx.x & 31;
    if (w >= NN) return;
    int n = w;
    int start = d_rowstart[n], deg = d_deg[n];
    float4* outp = (float4*)(d_h1 + (size_t)n * C1);
    if (deg == 0) {
        float4 z = make_float4(0, 0, 0, 0);
        outp[lane * 2] = z;
        outp[lane * 2 + 1] = z;
        return;
    }
    float4 el = *(const float4*)(d_el1 + n * 4);
    float4 ab = make_float4(ab1[0], ab1[1], ab1[2], ab1[3]);
    float4 elb = f4add(el, ab);
    // phase 1: max
    float4 mx = f4make(-INFINITY);
    for (int i = lane; i < deg; i += 32) {
        int s = d_csr[start + i];
        float4 er = *(const float4*)(d_er1 + s * 4);
        mx = f4max(mx, f4leaky(f4add(elb, er)));
    }
#pragma unroll
    for (int off = 16; off; off >>= 1) {
        mx.x = fmaxf(mx.x, __shfl_xor_sync(0xffffffffu, mx.x, off));
        mx.y = fmaxf(mx.y, __shfl_xor_sync(0xffffffffu, mx.y, off));
        mx.z = fmaxf(mx.z, __shfl_xor_sync(0xffffffffu, mx.z, off));
        mx.w = fmaxf(mx.w, __shfl_xor_sync(0xffffffffu, mx.w, off));
    }
    // phase 2: sum of exp
    float4 se = f4make(0.f);
    for (int i = lane; i < deg; i += 32) {
        int s = d_csr[start + i];
        float4 er = *(const float4*)(d_er1 + s * 4);
        float4 e = f4leaky(f4add(elb, er));
        se = f4add(se, f4expsub(e, mx));
    }
#pragma unroll
    for (int off = 16; off; off >>= 1) {
        se.x += __shfl_xor_sync(0xffffffffu, se.x, off);
        se.y += __shfl_xor_sync(0xffffffffu, se.y, off);
        se.z += __shfl_xor_sync(0xffffffffu, se.z, off);
        se.w += __shfl_xor_sync(0xffffffffu, se.w, off);
    }
    // phase 3: lane owns 8 contiguous bf16 cols lane*8..+7; head = lane>>3
    int h = lane >> 3;
    float mh = pick4(mx, h);
    float ih = 1.f / pick4(se, h);
    float ebh = pick4(elb, h);
    float acc[8] = {};
    const int* cp = d_csr + start;
    for (int i = 0; i < deg; i++) {
        int s = cp[i];
        float4 er = *(const float4*)(d_er1 + s * 4);
        float e = ebh + pick4(er, h);
        e = fmaxf(e, 0.2f * e);
        float al = __expf(e - mh) * ih;
        uint4 raw = *(const uint4*)&d_Wh1b[(size_t)s * C1 + lane * 8];
        float2 f0 = __bfloat1622float2(*reinterpret_cast<__nv_bfloat162*>(&raw.x));
        float2 f1 = __bfloat1622float2(*reinterpret_cast<__nv_bfloat162*>(&raw.y));
        float2 f2 = __bfloat1622float2(*reinterpret_cast<__nv_bfloat162*>(&raw.z));
        float2 f3 = __bfloat1622float2(*reinterpret_cast<__nv_bfloat162*>(&raw.w));
        acc[0] = fmaf(al, f0.x, acc[0]); acc[1] = fmaf(al, f0.y, acc[1]);
        acc[2] = fmaf(al, f1.x, acc[2]); acc[3] = fmaf(al, f1.y, acc[3]);
        acc[4] = fmaf(al, f2.x, acc[4]); acc[5] = fmaf(al, f2.y, acc[5]);
        acc[6] = fmaf(al, f3.x, acc[6]); acc[7] = fmaf(al, f3.y, acc[7]);
    }
    // fused ELU
    float4 o0 = make_float4(eluf(acc[0]), eluf(acc[1]), eluf(acc[2]), eluf(acc[3]));
    float4 o1 = make_float4(eluf(acc[4]), eluf(acc[5]), eluf(acc[6]), eluf(acc[7]));
    outp[lane * 2] = o0;
    outp[lane * 2 + 1] = o1;
}

// ---- GEMM2: Wh2[n, h*16+o] = h1[n,:]@W2 + b2 ; epilogue: bf16 store + el2/er2 ----
__global__ __launch_bounds__(256) void k_gemm2(const float* __restrict__ W2,
                                               const float* __restrict__ B2,
                                               const float* __restrict__ A2) {
    __shared__ float As[128][64];
    __shared__ float Bs[128][C2];
    __shared__ float sEl[64][16];
    __shared__ float sEr[64][16];
    int m0 = blockIdx.x * 64, tid = threadIdx.x;
    int tx = tid & 15, ty = tid >> 4;
    float acc[4][4] = {};
    for (int kc = 0; kc < 256; kc += 128) {
        {
            int m = tid & 63, kq = tid >> 6;
            int gm = m0 + m;
            bool ok = gm < NN;
            const float4* hp = (const float4*)(d_h1 + (size_t)gm * C1 + kc);
#pragma unroll
            for (int ll = 0; ll < 8; ll++) {
                int k4 = kq + ll * 4;
                float4 v = ok ? hp[k4] : make_float4(0, 0, 0, 0);
                As[k4 * 4 + 0][m] = v.x;
                As[k4 * 4 + 1][m] = v.y;
                As[k4 * 4 + 2][m] = v.z;
                As[k4 * 4 + 3][m] = v.w;
            }
        }
        {
            int o4 = tid & 15, k0 = tid >> 4;
            int c0 = o4 * 4;
            int hh = c0 >> 4, oo = c0 & 15;
#pragma unroll
            for (int kk = 0; kk < 8; kk++) {
                int k = k0 + kk * 16;
                *(float4*)&Bs[k][c0] =
                    *(const float4*)(W2 + (size_t)hh * 256 * 16 + (size_t)(kc + k) * 16 + oo);
            }
        }
        __syncthreads();
#pragma unroll 16
        for (int k = 0; k < 128; k++) {
            float4 a = *(const float4*)&As[k][ty * 4];
            float4 b = *(const float4*)&Bs[k][tx * 4];
            float av[4] = {a.x, a.y, a.z, a.w};
            float bv[4] = {b.x, b.y, b.z, b.w};
#pragma unroll
            for (int i = 0; i < 4; i++)
#pragma unroll
                for (int j = 0; j < 4; j++) acc[i][j] = fmaf(av[i], bv[j], acc[i][j]);
        }
        __syncthreads();
    }
    int c0 = tx * 4;
    int hh = tx >> 2;          // head of this thread's 4 cols
    int oo = (tx & 3) * 4;     // o offset within head
    float4 bias = *(const float4*)(B2 + c0);
    float bb[4] = {bias.x, bias.y, bias.z, bias.w};
    float4 a2d = *(const float4*)(A2 + hh * 32 + oo);
    float4 a2s = *(const float4*)(A2 + hh * 32 + 16 + oo);
    float ad[4] = {a2d.x, a2d.y, a2d.z, a2d.w};
    float asr[4] = {a2s.x, a2s.y, a2s.z, a2s.w};
#pragma unroll
    for (int i = 0; i < 4; i++) {
        int gm = m0 + ty * 4 + i;
        float o0 = acc[i][0] + bb[0], o1 = acc[i][1] + bb[1];
        float o2 = acc[i][2] + bb[2], o3 = acc[i][3] + bb[3];
        sEl[ty * 4 + i][tx] = o0 * ad[0] + o1 * ad[1] + o2 * ad[2] + o3 * ad[3];
        sEr[ty * 4 + i][tx] = o0 * asr[0] + o1 * asr[1] + o2 * asr[2] + o3 * asr[3];
        if (gm < NN) {
            uint2 pk = make_uint2(pack_bf2(o0, o1), pack_bf2(o2, o3));
            *(uint2*)&d_Wh2b[(size_t)gm * C2 + c0] = pk;
        }
    }
    __syncthreads();
    if (tid < 256) {
        int row = tid >> 2, h = tid & 3;
        int gm = m0 + row;
        if (gm < NN) {
            float el = 0.f, er = 0.f;
#pragma unroll
            for (int q = 0; q < 4; q++) { el += sEl[row][h * 4 + q]; er += sEr[row][h * 4 + q]; }
            d_el2[gm * 4 + h] = el;
            d_er2[gm * 4 + h] = er;
        }
    }
}

// ---------------- layer-2 segment softmax + aggregation ----------------
__global__ __launch_bounds__(256) void k_agg2(const float* __restrict__ ab2) {
    int w = (blockIdx.x * blockDim.x + threadIdx.x) >> 5;
    int lane = threadIdx.x & 31;
    if (w >= NN) return;
    int n = w;
    int start = d_rowstart[n], deg = d_deg[n];
    float2* outp = (float2*)(d_out2 + (size_t)n * C2);
    if (deg == 0) {
        outp[lane] = make_float2(0.f, 0.f);
        return;
    }
    float4 el = *(const float4*)(d_el2 + n * 4);
    float4 ab = make_float4(ab2[0], ab2[1], ab2[2], ab2[3]);
    float4 elb = f4add(el, ab);
    float4 mx = f4make(-INFINITY);
    for (int i = lane; i < deg; i += 32) {
        int s = d_csr[start + i];
        float4 er = *(const float4*)(d_er2 + s * 4);
        mx = f4max(mx, f4leaky(f4add(elb, er)));
    }
#pragma unroll
    for (int off = 16; off; off >>= 1) {
        mx.x = fmaxf(mx.x, __shfl_xor_sync(0xffffffffu, mx.x, off));
        mx.y = fmaxf(mx.y, __shfl_xor_sync(0xffffffffu, mx.y, off));
        mx.z = fmaxf(mx.z, __shfl_xor_sync(0xffffffffu, mx.z, off));
        mx.w = fmaxf(mx.w, __shfl_xor_sync(0xffffffffu, mx.w, off));
    }
    float4 se = f4make(0.f);
    for (int i = lane; i < deg; i += 32) {
        int s = d_csr[start + i];
        float4 er = *(const float4*)(d_er2 + s * 4);
        float4 e = f4leaky(f4add(elb, er));
        se = f4add(se, f4expsub(e, mx));
    }
#pragma unroll
    for (int off = 16; off; off >>= 1) {
        se.x += __shfl_xor_sync(0xffffffffu, se.x, off);
        se.y += __shfl_xor_sync(0xffffffffu, se.y, off);
        se.z += __shfl_xor_sync(0xffffffffu, se.z, off);
        se.w += __shfl_xor_sync(0xffffffffu, se.w, off);
    }
    // lane owns bf16 cols [2*lane, 2*lane+1]; head = lane>>3
    int h = lane >> 3;
    float mh = pick4(mx, h);
    float ih = 1.f / pick4(se, h);
    float ebh = pick4(elb, h);
    float2 acc = make_float2(0.f, 0.f);
    const int* cp = d_csr + start;
    for (int i = 0; i < deg; i++) {
        int s = cp[i];
        float4 er = *(const float4*)(d_er2 + s * 4);
        float e = ebh + pick4(er, h);
        e = fmaxf(e, 0.2f * e);
        float al = __expf(e - mh) * ih;
        __nv_bfloat162 wv = *(const __nv_bfloat162*)&d_Wh2b[(size_t)s * C2 + lane * 2];
        float2 wf = __bfloat1622float2(wv);
        acc.x = fmaf(al, wf.x, acc.x);
        acc.y = fmaf(al, wf.y, acc.y);
    }
    outp[lane] = acc;
}

// ---------------- readout: head-mean -> softmax -> node-mean ----------------
__global__ void k_final() {
    __shared__ float ssum[NCLS];
    if (threadIdx.x < NCLS) ssum[threadIdx.x] = 0.f;
    __syncthreads();
    float loc[NCLS];
#pragma unroll
    for (int k = 0; k < NCLS; k++) loc[k] = 0.f;
    for (int n = blockIdx.x * blockDim.x + threadIdx.x; n < NN;
         n += gridDim.x * blockDim.x) {
        const float* row = d_out2 + (size_t)n * C2;
        float z[NCLS];
#pragma unroll
        for (int k = 0; k < NCLS; k++)
            z[k] = 0.25f * (row[k] + row[16 + k] + row[32 + k] + row[48 + k]);
        float mx = z[0];
#pragma unroll
        for (int k = 1; k < NCLS; k++) mx = fmaxf(mx, z[k]);
        float s = 0.f;
#pragma unroll
        for (int k = 0; k < NCLS; k++) {
            z[k] = __expf(z[k] - mx);
            s += z[k];
        }
        float invs = 1.f / s;
#pragma unroll
        for (int k = 0; k < NCLS; k++) loc[k] += z[k] * invs;
    }
#pragma unroll
    for (int k = 0; k < NCLS; k++) atomicAdd(&ssum[k], loc[k]);
    __syncthreads();
    if (threadIdx.x < NCLS) atomicAdd(&d_cls[threadIdx.x], ssum[threadIdx.x]);
}

__global__ void k_fc(const float* __restrict__ fcw, const float* __restrict__ fcb,
                     float* __restrict__ out) {
    int c = threadIdx.x;
    if (c < NCLS) {
        float s = fcb[c];
        const float scale = 1.f / (float)NN;
#pragma unroll
        for (int k = 0; k < NCLS; k++) s = fmaf(d_cls[k] * scale, fcw[c * NCLS + k], s);
        out[c] = s;
    }
}

// ---------------- launch ----------------
extern "C" void kernel_launch(void* const* d_in, const int* in_sizes, int n_in,
                              void* d_out, int out_size) {
    const float* h   = (const float*)d_in[0];
    const int*   src = (const int*)d_in[1];
    const int*   dst = (const int*)d_in[2];
    const float* W1  = (const float*)d_in[3];
    const float* b1  = (const float*)d_in[4];
    const float* a1  = (const float*)d_in[5];
    const float* ab1 = (const float*)d_in[6];
    const float* W2  = (const float*)d_in[7];
    const float* b2  = (const float*)d_in[8];
    const float* a2  = (const float*)d_in[9];
    const float* ab2 = (const float*)d_in[10];
    const float* fcw = (const float*)d_in[11];
    const float* fcb = (const float*)d_in[12];
    float* out = (float*)d_out;

    k_init<<<(NN + 255) / 256, 256>>>();                       // 0
    k_hist<<<(NE + 255) / 256, 256>>>(dst);                    // 1
    k_chunkred<<<NCH, 256>>>();                                // 2
    k_gemm1<<<dim3((NN + 63) / 64, HEADS), 256>>>(h, W1, b1, a1);  // 3 (ncu slot)
    k_scanlocal<<<NCH, 256>>>();                               // 4
    k_scatter<<<(NE + 255) / 256, 256>>>(src, dst);            // 5
    k_agg1<<<(NN * 32 + 255) / 256, 256>>>(ab1);               // 6
    k_gemm2<<<(NN + 63) / 64, 256>>>(W2, b2, a2);              // 7
    k_agg2<<<(NN * 32 + 255) / 256, 256>>>(ab2);               // 8
    k_final<<<400, 256>>>();                                   // 9
    k_fc<<<1, 32>>>(fcw, fcb, out);                            // 10
}

// round 8
// speedup vs baseline: 1.3910x; 1.1402x over previous
#include <cuda_runtime.h>
#include <cuda_bf16.h>
#include <math.h>

#define NN 100000
#define NE 1600000
#define INF_ 128
#define HID 64
#define HEADS 4
#define NCLS 16
#define C1 256   // HEADS*HID
#define C2 64    // HEADS*NCLS
#define NCH 98   // ceil(NN/1024)

// ---------------- scratch (static device memory; no allocations) ----------------
__device__ __align__(16) __nv_bfloat16 d_Wh1b[(size_t)NN * C1];
__device__ __align__(16) __nv_bfloat16 d_h1b[(size_t)NN * C1];   // ELU(agg1), bf16
__device__ __align__(16) __nv_bfloat16 d_Wh2b[(size_t)NN * C2];
__device__ __align__(16) float d_out2[(size_t)NN * C2];
__device__ __align__(16) float d_el1[NN * HEADS];
__device__ __align__(16) float d_er1[NN * HEADS];
__device__ __align__(16) float d_el2[NN * HEADS];
__device__ __align__(16) float d_er2[NN * HEADS];
__device__ int   d_deg[NN];
__device__ int   d_rowstart[NN];
__device__ int   d_cursor[NN];
__device__ int   d_csr[NE];
__device__ int   d_csum[128];
__device__ float d_cls[NCLS];

// ---------------- small helpers ----------------
__device__ __forceinline__ float4 f4make(float v) { return make_float4(v, v, v, v); }
__device__ __forceinline__ float4 f4add(float4 a, float4 b) {
    return make_float4(a.x + b.x, a.y + b.y, a.z + b.z, a.w + b.w);
}
__device__ __forceinline__ float4 f4leaky(float4 a) {
    return make_float4(fmaxf(a.x, 0.2f * a.x), fmaxf(a.y, 0.2f * a.y),
                       fmaxf(a.z, 0.2f * a.z), fmaxf(a.w, 0.2f * a.w));
}
__device__ __forceinline__ float4 f4max(float4 a, float4 b) {
    return make_float4(fmaxf(a.x, b.x), fmaxf(a.y, b.y), fmaxf(a.z, b.z), fmaxf(a.w, b.w));
}
__device__ __forceinline__ float4 f4expsub(float4 e, float4 m) {
    return make_float4(__expf(e.x - m.x), __expf(e.y - m.y),
                       __expf(e.z - m.z), __expf(e.w - m.w));
}
__device__ __forceinline__ float pick4(float4 v, int h) {
    float r = v.x;
    if (h == 1) r = v.y;
    if (h == 2) r = v.z;
    if (h == 3) r = v.w;
    return r;
}
__device__ __forceinline__ unsigned pack_bf2(float a, float b) {
    __nv_bfloat162 t = __floats2bfloat162_rn(a, b);
    return *reinterpret_cast<unsigned*>(&t);
}
__device__ __forceinline__ float eluf(float x) { return x > 0.f ? x : expm1f(x); }
__device__ __forceinline__ float lo64(unsigned long long v) {
    return __uint_as_float((unsigned)v);
}
__device__ __forceinline__ float hi64(unsigned long long v) {
    return __uint_as_float((unsigned)(v >> 32));
}
#define FMA2(c, a, b) asm("fma.rn.f32x2 %0, %1, %2, %0;" : "+l"(c) : "l"(a), "l"(b))
#define SPLAT2(dst, f) asm("mov.b64 %0, {%1, %1};" : "=l"(dst) : "r"(__float_as_uint(f)))

// ---------------- init ----------------
__global__ void k_init() {
    int i = blockIdx.x * blockDim.x + threadIdx.x;
    if (i < NN) d_deg[i] = 0;
    if (i < NCLS) d_cls[i] = 0.f;
}

// ---------------- CSR build ----------------
__global__ void k_hist(const int* __restrict__ dst) {
    int e = blockIdx.x * blockDim.x + threadIdx.x;
    if (e < NE) atomicAdd(&d_deg[dst[e]], 1);
}

__global__ void k_chunkred() {   // d_csum[c] = total degree of chunk c
    int c = blockIdx.x, base = c * 1024;
    int s = 0;
    for (int i = threadIdx.x; i < 1024; i += 256) {
        int idx = base + i;
        if (idx < NN) s += d_deg[idx];
    }
    for (int o = 16; o; o >>= 1) s += __shfl_xor_sync(0xffffffffu, s, o);
    __shared__ int ws[8];
    if ((threadIdx.x & 31) == 0) ws[threadIdx.x >> 5] = s;
    __syncthreads();
    if (threadIdx.x == 0) {
        int t = 0;
        for (int i = 0; i < 8; i++) t += ws[i];
        d_csum[c] = t;
    }
}

__global__ void k_scanlocal() {
    int c = blockIdx.x, base = c * 1024, tid = threadIdx.x;
    __shared__ int s_off;
    {
        int part = 0;
        for (int t = tid; t < c; t += 256) part += d_csum[t];
        for (int o = 16; o; o >>= 1) part += __shfl_xor_sync(0xffffffffu, part, o);
        __shared__ int wsum[8];
        if ((tid & 31) == 0) wsum[tid >> 5] = part;
        __syncthreads();
        if (tid == 0) {
            int a = 0;
            for (int k = 0; k < 8; k++) a += wsum[k];
            s_off = a;
        }
        __syncthreads();
    }
    int v[4];
    int i0 = base + tid * 4;
#pragma unroll
    for (int j = 0; j < 4; j++) v[j] = (i0 + j < NN) ? d_deg[i0 + j] : 0;
    int ts = v[0] + v[1] + v[2] + v[3];
    int lane = tid & 31, wp = tid >> 5;
    int x = ts;
#pragma unroll
    for (int o = 1; o < 32; o <<= 1) {
        int y = __shfl_up_sync(0xffffffffu, x, o);
        if (lane >= o) x += y;
    }
    __shared__ int ws[8], wo[8];
    if (lane == 31) ws[wp] = x;
    __syncthreads();
    if (tid == 0) {
        int a = 0;
        for (int k = 0; k < 8; k++) { wo[k] = a; a += ws[k]; }
    }
    __syncthreads();
    int run = s_off + wo[wp] + (x - ts);
#pragma unroll
    for (int j = 0; j < 4; j++) {
        if (i0 + j < NN) {
            d_rowstart[i0 + j] = run;
            d_cursor[i0 + j] = run;
            run += v[j];
        }
    }
}

__global__ void k_scatter(const int* __restrict__ src, const int* __restrict__ dst) {
    int e = blockIdx.x * blockDim.x + threadIdx.x;
    if (e < NE) {
        int d = dst[e];
        int p = atomicAdd(&d_cursor[d], 1);
        d_csr[p] = src[e];
    }
}

// ---- GEMM1: [NN,128] @ [128,256], 128x128 tile, 8x8 microtile, f32x2 FMA ----
// grid (782, 2): y = column half (2 heads). Epilogue: bf16 store + el/er via shfl.
__global__ __launch_bounds__(256) void k_gemm1(const float* __restrict__ H,
                                               const float* __restrict__ W1,
                                               const float* __restrict__ B1,
                                               const float* __restrict__ A1) {
    __shared__ __align__(16) float As[32][128];
    __shared__ __align__(16) float Bs[32][128];
    int m0 = blockIdx.x * 128;
    int c0 = blockIdx.y * 128;
    int h0 = blockIdx.y * 2, h1 = h0 + 1;
    int tid = threadIdx.x;
    int tx = tid & 15, ty = tid >> 4;
    unsigned long long acc[8][4];
#pragma unroll
    for (int i = 0; i < 8; i++)
#pragma unroll
        for (int j = 0; j < 4; j++) acc[i][j] = 0ull;

    for (int kc = 0; kc < 128; kc += 32) {
        // stage A: [32 k][128 m] transposed; lanes over m (conflict-free STS)
#pragma unroll
        for (int t = 0; t < 4; t++) {
            int i = tid + t * 256;
            int m = i & 127, k4 = i >> 7;
            int gm = m0 + m;
            float4 v = (gm < NN) ? *(const float4*)(H + (size_t)gm * 128 + kc + k4 * 4)
                                 : make_float4(0, 0, 0, 0);
            As[k4 * 4 + 0][m] = v.x;
            As[k4 * 4 + 1][m] = v.y;
            As[k4 * 4 + 2][m] = v.z;
            As[k4 * 4 + 3][m] = v.w;
        }
        // stage B: [32 k][128 c]
#pragma unroll
        for (int t = 0; t < 4; t++) {
            int i = tid + t * 256;
            int k = i >> 5, c4 = (i & 31) * 4;
            int c = c0 + c4, hh = c >> 6, oo = c & 63;
            *(float4*)&Bs[k][c4] =
                *(const float4*)(W1 + (size_t)hh * 8192 + (size_t)(kc + k) * 64 + oo);
        }
        __syncthreads();
#pragma unroll 8
        for (int k = 0; k < 32; k++) {
            float4 av0 = *(const float4*)&As[k][ty * 8];
            float4 av1 = *(const float4*)&As[k][ty * 8 + 4];
            ulonglong2 bA = *(const ulonglong2*)&Bs[k][tx * 4];
            ulonglong2 bB = *(const ulonglong2*)&Bs[k][64 + tx * 4];
            float aa[8] = {av0.x, av0.y, av0.z, av0.w, av1.x, av1.y, av1.z, av1.w};
#pragma unroll
            for (int i = 0; i < 8; i++) {
                unsigned long long a2v;
                SPLAT2(a2v, aa[i]);
                FMA2(acc[i][0], a2v, bA.x);
                FMA2(acc[i][1], a2v, bA.y);
                FMA2(acc[i][2], a2v, bB.x);
                FMA2(acc[i][3], a2v, bB.y);
            }
        }
        __syncthreads();
    }
    // epilogue: bias, bf16 store, el/er partial + butterfly over 16 tx lanes
    int o = tx * 4;
    float4 bb0 = *(const float4*)(B1 + h0 * 64 + o);
    float4 bb1 = *(const float4*)(B1 + h1 * 64 + o);
    float4 ad0 = *(const float4*)(A1 + h0 * 128 + o);
    float4 as0 = *(const float4*)(A1 + h0 * 128 + 64 + o);
    float4 ad1 = *(const float4*)(A1 + h1 * 128 + o);
    float4 as1 = *(const float4*)(A1 + h1 * 128 + 64 + o);
#pragma unroll
    for (int i = 0; i < 8; i++) {
        int gm = m0 + ty * 8 + i;
        float o00 = lo64(acc[i][0]) + bb0.x, o01 = hi64(acc[i][0]) + bb0.y;
        float o02 = lo64(acc[i][1]) + bb0.z, o03 = hi64(acc[i][1]) + bb0.w;
        float o10 = lo64(acc[i][2]) + bb1.x, o11 = hi64(acc[i][2]) + bb1.y;
        float o12 = lo64(acc[i][3]) + bb1.z, o13 = hi64(acc[i][3]) + bb1.w;
        float pElA = o00 * ad0.x + o01 * ad0.y + o02 * ad0.z + o03 * ad0.w;
        float pErA = o00 * as0.x + o01 * as0.y + o02 * as0.z + o03 * as0.w;
        float pElB = o10 * ad1.x + o11 * ad1.y + o12 * ad1.z + o13 * ad1.w;
        float pErB = o10 * as1.x + o11 * as1.y + o12 * as1.z + o13 * as1.w;
#pragma unroll
        for (int off = 8; off; off >>= 1) {
            pElA += __shfl_xor_sync(0xffffffffu, pElA, off);
            pErA += __shfl_xor_sync(0xffffffffu, pErA, off);
            pElB += __shfl_xor_sync(0xffffffffu, pElB, off);
            pErB += __shfl_xor_sync(0xffffffffu, pErB, off);
        }
        if (gm < NN) {
            *(uint2*)&d_Wh1b[(size_t)gm * C1 + h0 * 64 + o] =
                make_uint2(pack_bf2(o00, o01), pack_bf2(o02, o03));
            *(uint2*)&d_Wh1b[(size_t)gm * C1 + h1 * 64 + o] =
                make_uint2(pack_bf2(o10, o11), pack_bf2(o12, o13));
            if (tx == 0) {
                d_el1[gm * 4 + h0] = pElA;
                d_er1[gm * 4 + h0] = pErA;
                d_el1[gm * 4 + h1] = pElB;
                d_er1[gm * 4 + h1] = pErB;
            }
        }
    }
}

// ---------------- layer-1 segment softmax + aggregation (warp per dst node) ------
__global__ __launch_bounds__(256) void k_agg1(const float* __restrict__ ab1) {
    int w = (blockIdx.x * blockDim.x + threadIdx.x) >> 5;
    int lane = threadIdx.x & 31;
    if (w >= NN) return;
    int n = w;
    int start = d_rowstart[n], deg = d_deg[n];
    if (deg == 0) {
        *(uint4*)&d_h1b[(size_t)n * C1 + lane * 8] = make_uint4(0, 0, 0, 0);
        return;
    }
    float4 el = *(const float4*)(d_el1 + n * 4);
    float4 ab = make_float4(ab1[0], ab1[1], ab1[2], ab1[3]);
    float4 elb = f4add(el, ab);
    // phase 1: max
    float4 mx = f4make(-INFINITY);
    for (int i = lane; i < deg; i += 32) {
        int s = d_csr[start + i];
        float4 er = *(const float4*)(d_er1 + s * 4);
        mx = f4max(mx, f4leaky(f4add(elb, er)));
    }
#pragma unroll
    for (int off = 16; off; off >>= 1) {
        mx.x = fmaxf(mx.x, __shfl_xor_sync(0xffffffffu, mx.x, off));
        mx.y = fmaxf(mx.y, __shfl_xor_sync(0xffffffffu, mx.y, off));
        mx.z = fmaxf(mx.z, __shfl_xor_sync(0xffffffffu, mx.z, off));
        mx.w = fmaxf(mx.w, __shfl_xor_sync(0xffffffffu, mx.w, off));
    }
    // phase 2: sum of exp
    float4 se = f4make(0.f);
    for (int i = lane; i < deg; i += 32) {
        int s = d_csr[start + i];
        float4 er = *(const float4*)(d_er1 + s * 4);
        float4 e = f4leaky(f4add(elb, er));
        se = f4add(se, f4expsub(e, mx));
    }
#pragma unroll
    for (int off = 16; off; off >>= 1) {
        se.x += __shfl_xor_sync(0xffffffffu, se.x, off);
        se.y += __shfl_xor_sync(0xffffffffu, se.y, off);
        se.z += __shfl_xor_sync(0xffffffffu, se.z, off);
        se.w += __shfl_xor_sync(0xffffffffu, se.w, off);
    }
    // phase 3: lane owns 8 contiguous bf16 cols lane*8..+7; head = lane>>3
    int h = lane >> 3;
    float mh = pick4(mx, h);
    float ih = 1.f / pick4(se, h);
    float ebh = pick4(elb, h);
    float acc[8] = {};
    const int* cp = d_csr + start;
    for (int i = 0; i < deg; i++) {
        int s = cp[i];
        float4 er = *(const float4*)(d_er1 + s * 4);
        float e = ebh + pick4(er, h);
        e = fmaxf(e, 0.2f * e);
        float al = __expf(e - mh) * ih;
        uint4 raw = *(const uint4*)&d_Wh1b[(size_t)s * C1 + lane * 8];
        float2 f0 = __bfloat1622float2(*reinterpret_cast<__nv_bfloat162*>(&raw.x));
        float2 f1 = __bfloat1622float2(*reinterpret_cast<__nv_bfloat162*>(&raw.y));
        float2 f2 = __bfloat1622float2(*reinterpret_cast<__nv_bfloat162*>(&raw.z));
        float2 f3 = __bfloat1622float2(*reinterpret_cast<__nv_bfloat162*>(&raw.w));
        acc[0] = fmaf(al, f0.x, acc[0]); acc[1] = fmaf(al, f0.y, acc[1]);
        acc[2] = fmaf(al, f1.x, acc[2]); acc[3] = fmaf(al, f1.y, acc[3]);
        acc[4] = fmaf(al, f2.x, acc[4]); acc[5] = fmaf(al, f2.y, acc[5]);
        acc[6] = fmaf(al, f3.x, acc[6]); acc[7] = fmaf(al, f3.y, acc[7]);
    }
    // fused ELU + bf16 pack
    uint4 po;
    po.x = pack_bf2(eluf(acc[0]), eluf(acc[1]));
    po.y = pack_bf2(eluf(acc[2]), eluf(acc[3]));
    po.z = pack_bf2(eluf(acc[4]), eluf(acc[5]));
    po.w = pack_bf2(eluf(acc[6]), eluf(acc[7]));
    *(uint4*)&d_h1b[(size_t)n * C1 + lane * 8] = po;
}

// ---- GEMM2: [NN,256]bf16 @ [256,64], 128-row tile, 8x8 microtile, f32x2 ----
__global__ __launch_bounds__(128) void k_gemm2(const float* __restrict__ W2,
                                               const float* __restrict__ B2,
                                               const float* __restrict__ A2) {
    __shared__ __align__(16) float As[32][128];
    __shared__ __align__(16) float Bs[32][64];
    int m0 = blockIdx.x * 128;
    int tid = threadIdx.x;
    int tx = tid & 7, ty = tid >> 3;
    unsigned long long acc[8][4];
#pragma unroll
    for (int i = 0; i < 8; i++)
#pragma unroll
        for (int j = 0; j < 4; j++) acc[i][j] = 0ull;

    for (int kc = 0; kc < 256; kc += 32) {
        // stage A from bf16 h1: thread = row, t = k-octet
        {
            int gm = m0 + tid;
            bool ok = gm < NN;
#pragma unroll
            for (int t = 0; t < 4; t++) {
                uint4 raw = ok ? *(const uint4*)&d_h1b[(size_t)gm * C1 + kc + t * 8]
                               : make_uint4(0, 0, 0, 0);
                float2 f0 = __bfloat1622float2(*reinterpret_cast<__nv_bfloat162*>(&raw.x));
                float2 f1 = __bfloat1622float2(*reinterpret_cast<__nv_bfloat162*>(&raw.y));
                float2 f2 = __bfloat1622float2(*reinterpret_cast<__nv_bfloat162*>(&raw.z));
                float2 f3 = __bfloat1622float2(*reinterpret_cast<__nv_bfloat162*>(&raw.w));
                As[t * 8 + 0][tid] = f0.x; As[t * 8 + 1][tid] = f0.y;
                As[t * 8 + 2][tid] = f1.x; As[t * 8 + 3][tid] = f1.y;
                As[t * 8 + 4][tid] = f2.x; As[t * 8 + 5][tid] = f2.y;
                As[t * 8 + 6][tid] = f3.x; As[t * 8 + 7][tid] = f3.y;
            }
        }
        // stage B
#pragma unroll
        for (int t = 0; t < 4; t++) {
            int i = tid + t * 128;
            int k = i >> 4, c4 = (i & 15) * 4;
            int hh = c4 >> 4, oo = c4 & 15;
            *(float4*)&Bs[k][c4] =
                *(const float4*)(W2 + (size_t)hh * 4096 + (size_t)(kc + k) * 16 + oo);
        }
        __syncthreads();
#pragma unroll 8
        for (int k = 0; k < 32; k++) {
            float4 av0 = *(const float4*)&As[k][ty * 8];
            float4 av1 = *(const float4*)&As[k][ty * 8 + 4];
            ulonglong2 bA = *(const ulonglong2*)&Bs[k][tx * 4];
            ulonglong2 bB = *(const ulonglong2*)&Bs[k][32 + tx * 4];
            float aa[8] = {av0.x, av0.y, av0.z, av0.w, av1.x, av1.y, av1.z, av1.w};
#pragma unroll
            for (int i = 0; i < 8; i++) {
                unsigned long long a2v;
                SPLAT2(a2v, aa[i]);
                FMA2(acc[i][0], a2v, bA.x);
                FMA2(acc[i][1], a2v, bA.y);
                FMA2(acc[i][2], a2v, bB.x);
                FMA2(acc[i][3], a2v, bB.y);
            }
        }
        __syncthreads();
    }
    // epilogue: group0 cols tx*4 (head tx>>2), group1 cols 32+tx*4 (head 2+(tx>>2))
    int hA = tx >> 2, hB = 2 + (tx >> 2);
    int o = (tx & 3) * 4;
    float4 bbA = *(const float4*)(B2 + hA * 16 + o);
    float4 bbB = *(const float4*)(B2 + hB * 16 + o);
    float4 adA = *(const float4*)(A2 + hA * 32 + o);
    float4 asA = *(const float4*)(A2 + hA * 32 + 16 + o);
    float4 adB = *(const float4*)(A2 + hB * 32 + o);
    float4 asB = *(const float4*)(A2 + hB * 32 + 16 + o);
#pragma unroll
    for (int i = 0; i < 8; i++) {
        int gm = m0 + ty * 8 + i;
        float o00 = lo64(acc[i][0]) + bbA.x, o01 = hi64(acc[i][0]) + bbA.y;
        float o02 = lo64(acc[i][1]) + bbA.z, o03 = hi64(acc[i][1]) + bbA.w;
        float o10 = lo64(acc[i][2]) + bbB.x, o11 = hi64(acc[i][2]) + bbB.y;
        float o12 = lo64(acc[i][3]) + bbB.z, o13 = hi64(acc[i][3]) + bbB.w;
        float pElA = o00 * adA.x + o01 * adA.y + o02 * adA.z + o03 * adA.w;
        float pErA = o00 * asA.x + o01 * asA.y + o02 * asA.z + o03 * asA.w;
        float pElB = o10 * adB.x + o11 * adB.y + o12 * adB.z + o13 * adB.w;
        float pErB = o10 * asB.x + o11 * asB.y + o12 * asB.z + o13 * asB.w;
#pragma unroll
        for (int off = 2; off; off >>= 1) {
            pElA += __shfl_xor_sync(0xffffffffu, pElA, off);
            pErA += __shfl_xor_sync(0xffffffffu, pErA, off);
            pElB += __shfl_xor_sync(0xffffffffu, pElB, off);
            pErB += __shfl_xor_sync(0xffffffffu, pErB, off);
        }
        if (gm < NN) {
            *(uint2*)&d_Wh2b[(size_t)gm * C2 + tx * 4] =
                make_uint2(pack_bf2(o00, o01), pack_bf2(o02, o03));
            *(uint2*)&d_Wh2b[(size_t)gm * C2 + 32 + tx * 4] =
                make_uint2(pack_bf2(o10, o11), pack_bf2(o12, o13));
            if ((tx & 3) == 0) {
                d_el2[gm * 4 + hA] = pElA;
                d_er2[gm * 4 + hA] = pErA;
                d_el2[gm * 4 + hB] = pElB;
                d_er2[gm * 4 + hB] = pErB;
            }
        }
    }
}

// ---------------- layer-2 segment softmax + aggregation ----------------
__global__ __launch_bounds__(256) void k_agg2(const float* __restrict__ ab2) {
    int w = (blockIdx.x * blockDim.x + threadIdx.x) >> 5;
    int lane = threadIdx.x & 31;
    if (w >= NN) return;
    int n = w;
    int start = d_rowstart[n], deg = d_deg[n];
    float2* outp = (float2*)(d_out2 + (size_t)n * C2);
    if (deg == 0) {
        outp[lane] = make_float2(0.f, 0.f);
        return;
    }
    float4 el = *(const float4*)(d_el2 + n * 4);
    float4 ab = make_float4(ab2[0], ab2[1], ab2[2], ab2[3]);
    float4 elb = f4add(el, ab);
    float4 mx = f4make(-INFINITY);
    for (int i = lane; i < deg; i += 32) {
        int s = d_csr[start + i];
        float4 er = *(const float4*)(d_er2 + s * 4);
        mx = f4max(mx, f4leaky(f4add(elb, er)));
    }
#pragma unroll
    for (int off = 16; off; off >>= 1) {
        mx.x = fmaxf(mx.x, __shfl_xor_sync(0xffffffffu, mx.x, off));
        mx.y = fmaxf(mx.y, __shfl_xor_sync(0xffffffffu, mx.y, off));
        mx.z = fmaxf(mx.z, __shfl_xor_sync(0xffffffffu, mx.z, off));
        mx.w = fmaxf(mx.w, __shfl_xor_sync(0xffffffffu, mx.w, off));
    }
    float4 se = f4make(0.f);
    for (int i = lane; i < deg; i += 32) {
        int s = d_csr[start + i];
        float4 er = *(const float4*)(d_er2 + s * 4);
        float4 e = f4leaky(f4add(elb, er));
        se = f4add(se, f4expsub(e, mx));
    }
#pragma unroll
    for (int off = 16; off; off >>= 1) {
        se.x += __shfl_xor_sync(0xffffffffu, se.x, off);
        se.y += __shfl_xor_sync(0xffffffffu, se.y, off);
        se.z += __shfl_xor_sync(0xffffffffu, se.z, off);
        se.w += __shfl_xor_sync(0xffffffffu, se.w, off);
    }
    int h = lane >> 3;
    float mh = pick4(mx, h);
    float ih = 1.f / pick4(se, h);
    float ebh = pick4(elb, h);
    float2 acc = make_float2(0.f, 0.f);
    const int* cp = d_csr + start;
    for (int i = 0; i < deg; i++) {
        int s = cp[i];
        float4 er = *(const float4*)(d_er2 + s * 4);
        float e = ebh + pick4(er, h);
        e = fmaxf(e, 0.2f * e);
        float al = __expf(e - mh) * ih;
        __nv_bfloat162 wv = *(const __nv_bfloat162*)&d_Wh2b[(size_t)s * C2 + lane * 2];
        float2 wf = __bfloat1622float2(wv);
        acc.x = fmaf(al, wf.x, acc.x);
        acc.y = fmaf(al, wf.y, acc.y);
    }
    outp[lane] = acc;
}

// ---------------- readout: head-mean -> softmax -> node-mean ----------------
__global__ void k_final() {
    __shared__ float ssum[NCLS];
    if (threadIdx.x < NCLS) ssum[threadIdx.x] = 0.f;
    __syncthreads();
    float loc[NCLS];
#pragma unroll
    for (int k = 0; k < NCLS; k++) loc[k] = 0.f;
    for (int n = blockIdx.x * blockDim.x + threadIdx.x; n < NN;
         n += gridDim.x * blockDim.x) {
        const float* row = d_out2 + (size_t)n * C2;
        float z[NCLS];
#pragma unroll
        for (int k = 0; k < NCLS; k++)
            z[k] = 0.25f * (row[k] + row[16 + k] + row[32 + k] + row[48 + k]);
        float mx = z[0];
#pragma unroll
        for (int k = 1; k < NCLS; k++) mx = fmaxf(mx, z[k]);
        float s = 0.f;
#pragma unroll
        for (int k = 0; k < NCLS; k++) {
            z[k] = __expf(z[k] - mx);
            s += z[k];
        }
        float invs = 1.f / s;
#pragma unroll
        for (int k = 0; k < NCLS; k++) loc[k] += z[k] * invs;
    }
#pragma unroll
    for (int k = 0; k < NCLS; k++) atomicAdd(&ssum[k], loc[k]);
    __syncthreads();
    if (threadIdx.x < NCLS) atomicAdd(&d_cls[threadIdx.x], ssum[threadIdx.x]);
}

__global__ void k_fc(const float* __restrict__ fcw, const float* __restrict__ fcb,
                     float* __restrict__ out) {
    int c = threadIdx.x;
    if (c < NCLS) {
        float s = fcb[c];
        const float scale = 1.f / (float)NN;
#pragma unroll
        for (int k = 0; k < NCLS; k++) s = fmaf(d_cls[k] * scale, fcw[c * NCLS + k], s);
        out[c] = s;
    }
}

// ---------------- launch ----------------
extern "C" void kernel_launch(void* const* d_in, const int* in_sizes, int n_in,
                              void* d_out, int out_size) {
    const float* h   = (const float*)d_in[0];
    const int*   src = (const int*)d_in[1];
    const int*   dst = (const int*)d_in[2];
    const float* W1  = (const float*)d_in[3];
    const float* b1  = (const float*)d_in[4];
    const float* a1  = (const float*)d_in[5];
    const float* ab1 = (const float*)d_in[6];
    const float* W2  = (const float*)d_in[7];
    const float* b2  = (const float*)d_in[8];
    const float* a2  = (const float*)d_in[9];
    const float* ab2 = (const float*)d_in[10];
    const float* fcw = (const float*)d_in[11];
    const float* fcb = (const float*)d_in[12];
    float* out = (float*)d_out;

    k_init<<<(NN + 255) / 256, 256>>>();                           // 0
    k_hist<<<(NE + 255) / 256, 256>>>(dst);                        // 1
    k_chunkred<<<NCH, 256>>>();                                    // 2
    k_gemm1<<<dim3((NN + 127) / 128, 2), 256>>>(h, W1, b1, a1);    // 3 (ncu slot)
    k_scanlocal<<<NCH, 256>>>();                                   // 4
    k_scatter<<<(NE + 255) / 256, 256>>>(src, dst);                // 5
    k_agg1<<<(NN * 32 + 255) / 256, 256>>>(ab1);                   // 6
    k_gemm2<<<(NN + 127) / 128, 128>>>(W2, b2, a2);                // 7
    k_agg2<<<(NN * 32 + 255) / 256, 256>>>(ab2);                   // 8
    k_final<<<400, 256>>>();                                       // 9
    k_fc<<<1, 32>>>(fcw, fcb, out);                                // 10
}

// round 10
// speedup vs baseline: 1.4994x; 1.0779x over previous
#include <cuda_runtime.h>
#include <cuda_bf16.h>
#include <mma.h>
#include <math.h>

using namespace nvcuda;

#define NN 100000
#define NE 1600000
#define INF_ 128
#define HID 64
#define HEADS 4
#define NCLS 16
#define C1 256   // HEADS*HID
#define C2 64    // HEADS*NCLS
#define NCH 98   // ceil(NN/1024)

// ---------------- scratch (static device memory; no allocations) ----------------
__device__ __align__(16) __nv_bfloat16 d_Wh1b[(size_t)NN * C1];
__device__ __align__(16) __nv_bfloat16 d_h1b[(size_t)NN * C1];   // ELU(agg1), bf16
__device__ __align__(16) __nv_bfloat16 d_Wh2b[(size_t)NN * C2];
__device__ __align__(16) float d_out2[(size_t)NN * C2];
__device__ __align__(16) float d_el1[NN * HEADS];
__device__ __align__(16) float d_er1[NN * HEADS];
__device__ __align__(16) float d_el2[NN * HEADS];
__device__ __align__(16) float d_er2[NN * HEADS];
__device__ int   d_deg[NN];
__device__ int   d_rowstart[NN];
__device__ int   d_cursor[NN];
__device__ int   d_csr[NE];
__device__ int   d_csum[128];
__device__ float d_cls[NCLS];

// ---------------- small helpers ----------------
__device__ __forceinline__ float4 f4make(float v) { return make_float4(v, v, v, v); }
__device__ __forceinline__ float4 f4add(float4 a, float4 b) {
    return make_float4(a.x + b.x, a.y + b.y, a.z + b.z, a.w + b.w);
}
__device__ __forceinline__ float4 f4leaky(float4 a) {
    return make_float4(fmaxf(a.x, 0.2f * a.x), fmaxf(a.y, 0.2f * a.y),
                       fmaxf(a.z, 0.2f * a.z), fmaxf(a.w, 0.2f * a.w));
}
__device__ __forceinline__ float4 f4max(float4 a, float4 b) {
    return make_float4(fmaxf(a.x, b.x), fmaxf(a.y, b.y), fmaxf(a.z, b.z), fmaxf(a.w, b.w));
}
__device__ __forceinline__ float4 f4expsub(float4 e, float4 m) {
    return make_float4(__expf(e.x - m.x), __expf(e.y - m.y),
                       __expf(e.z - m.z), __expf(e.w - m.w));
}
__device__ __forceinline__ float pick4(float4 v, int h) {
    float r = v.x;
    if (h == 1) r = v.y;
    if (h == 2) r = v.z;
    if (h == 3) r = v.w;
    return r;
}
__device__ __forceinline__ unsigned pack_bf2(float a, float b) {
    __nv_bfloat162 t = __floats2bfloat162_rn(a, b);
    return *reinterpret_cast<unsigned*>(&t);
}
__device__ __forceinline__ float eluf(float x) { return x > 0.f ? x : expm1f(x); }
__device__ __forceinline__ float lo64(unsigned long long v) {
    return __uint_as_float((unsigned)v);
}
__device__ __forceinline__ float hi64(unsigned long long v) {
    return __uint_as_float((unsigned)(v >> 32));
}
#define FMA2(c, a, b) asm("fma.rn.f32x2 %0, %1, %2, %0;" : "+l"(c) : "l"(a), "l"(b))
#define SPLAT2(dst, f) asm("mov.b64 %0, {%1, %1};" : "=l"(dst) : "r"(__float_as_uint(f)))

// ---------------- init ----------------
__global__ void k_init() {
    int i = blockIdx.x * blockDim.x + threadIdx.x;
    if (i < NN) d_deg[i] = 0;
    if (i < NCLS) d_cls[i] = 0.f;
}

// ---------------- CSR build ----------------
__global__ void k_hist(const int* __restrict__ dst) {
    int e = blockIdx.x * blockDim.x + threadIdx.x;
    if (e < NE) atomicAdd(&d_deg[dst[e]], 1);
}

__global__ void k_chunkred() {   // d_csum[c] = total degree of chunk c
    int c = blockIdx.x, base = c * 1024;
    int s = 0;
    for (int i = threadIdx.x; i < 1024; i += 256) {
        int idx = base + i;
        if (idx < NN) s += d_deg[idx];
    }
    for (int o = 16; o; o >>= 1) s += __shfl_xor_sync(0xffffffffu, s, o);
    __shared__ int ws[8];
    if ((threadIdx.x & 31) == 0) ws[threadIdx.x >> 5] = s;
    __syncthreads();
    if (threadIdx.x == 0) {
        int t = 0;
        for (int i = 0; i < 8; i++) t += ws[i];
        d_csum[c] = t;
    }
}

__global__ void k_scanlocal() {
    int c = blockIdx.x, base = c * 1024, tid = threadIdx.x;
    __shared__ int s_off;
    {
        int part = 0;
        for (int t = tid; t < c; t += 256) part += d_csum[t];
        for (int o = 16; o; o >>= 1) part += __shfl_xor_sync(0xffffffffu, part, o);
        __shared__ int wsum[8];
        if ((tid & 31) == 0) wsum[tid >> 5] = part;
        __syncthreads();
        if (tid == 0) {
            int a = 0;
            for (int k = 0; k < 8; k++) a += wsum[k];
            s_off = a;
        }
        __syncthreads();
    }
    int v[4];
    int i0 = base + tid * 4;
#pragma unroll
    for (int j = 0; j < 4; j++) v[j] = (i0 + j < NN) ? d_deg[i0 + j] : 0;
    int ts = v[0] + v[1] + v[2] + v[3];
    int lane = tid & 31, wp = tid >> 5;
    int x = ts;
#pragma unroll
    for (int o = 1; o < 32; o <<= 1) {
        int y = __shfl_up_sync(0xffffffffu, x, o);
        if (lane >= o) x += y;
    }
    __shared__ int ws[8], wo[8];
    if (lane == 31) ws[wp] = x;
    __syncthreads();
    if (tid == 0) {
        int a = 0;
        for (int k = 0; k < 8; k++) { wo[k] = a; a += ws[k]; }
    }
    __syncthreads();
    int run = s_off + wo[wp] + (x - ts);
#pragma unroll
    for (int j = 0; j < 4; j++) {
        if (i0 + j < NN) {
            d_rowstart[i0 + j] = run;
            d_cursor[i0 + j] = run;
            run += v[j];
        }
    }
}

__global__ void k_scatter(const int* __restrict__ src, const int* __restrict__ dst) {
    int e = blockIdx.x * blockDim.x + threadIdx.x;
    if (e < NE) {
        int d = dst[e];
        int p = atomicAdd(&d_cursor[d], 1);
        d_csr[p] = src[e];
    }
}

// ---- GEMM1 (tensor core): [NN,128]bf16 @ [128,256]bf16 -> fp32, wmma m16n16k16 ----
// grid (782, 2): y = column half (2 heads). Block tile 128x128; 8 warps = 4(M)x2(N);
// warp tile 32x64 (one head in N). Epilogue: bias + bf16 store + el/er warp-local.
__global__ __launch_bounds__(256) void k_gemm1(const float* __restrict__ H,
                                               const float* __restrict__ W1,
                                               const float* __restrict__ B1,
                                               const float* __restrict__ A1) {
    __shared__ __align__(16) __nv_bfloat16 As[128][72];   // [m][k-chunk 64] pad 8
    __shared__ __align__(16) __nv_bfloat16 Bs[64][136];   // [k-chunk][c 128] pad 8
    __shared__ __align__(16) float Cbuf[8][16][20];       // per-warp frag staging
    int m0 = blockIdx.x * 128;
    int tid = threadIdx.x;
    int w = tid >> 5, lane = tid & 31;
    int warpM0 = (w & 3) * 32;
    int warpN0 = (w >> 2) * 64;                 // 0 or 64 within block tile
    int hd = blockIdx.y * 2 + (w >> 2);         // this warp's head

    wmma::fragment<wmma::accumulator, 16, 16, 16, float> cf[2][4];
#pragma unroll
    for (int mi = 0; mi < 2; mi++)
#pragma unroll
        for (int ni = 0; ni < 4; ni++) wmma::fill_fragment(cf[mi][ni], 0.f);

    for (int kc = 0; kc < 128; kc += 64) {
        // stage A (fp32 -> bf16): thread = (row, k-half of 32)
        {
            int row = tid >> 1, half = tid & 1;
            int gm = m0 + row;
            const float4* hp = (const float4*)(H + (size_t)gm * 128 + kc + half * 32);
            uint4* dstp = (uint4*)&As[row][half * 32];
            if (gm < NN) {
#pragma unroll
                for (int q = 0; q < 4; q++) {
                    float4 v0 = hp[2 * q], v1 = hp[2 * q + 1];
                    uint4 st;
                    st.x = pack_bf2(v0.x, v0.y);
                    st.y = pack_bf2(v0.z, v0.w);
                    st.z = pack_bf2(v1.x, v1.y);
                    st.w = pack_bf2(v1.z, v1.w);
                    dstp[q] = st;
                }
            } else {
#pragma unroll
                for (int q = 0; q < 4; q++) dstp[q] = make_uint4(0, 0, 0, 0);
            }
        }
        // stage B (fp32 -> bf16): thread = (k row, 32-col quarter)
        {
            int k = tid >> 2, qu = tid & 3;
            int c = qu * 32;
            int hh = blockIdx.y * 2 + (c >> 6);
            int oo = c & 63;
            const float4* wp = (const float4*)(W1 + (size_t)hh * 8192 + (size_t)(kc + k) * 64 + oo);
            uint4* dstp = (uint4*)&Bs[k][c];
#pragma unroll
            for (int q = 0; q < 4; q++) {
                float4 v0 = wp[2 * q], v1 = wp[2 * q + 1];
                uint4 st;
                st.x = pack_bf2(v0.x, v0.y);
                st.y = pack_bf2(v0.z, v0.w);
                st.z = pack_bf2(v1.x, v1.y);
                st.w = pack_bf2(v1.z, v1.w);
                dstp[q] = st;
            }
        }
        __syncthreads();
#pragma unroll
        for (int ks = 0; ks < 4; ks++) {
            wmma::fragment<wmma::matrix_a, 16, 16, 16, __nv_bfloat16, wmma::row_major> af[2];
#pragma unroll
            for (int mi = 0; mi < 2; mi++)
                wmma::load_matrix_sync(af[mi], &As[warpM0 + mi * 16][ks * 16], 72);
#pragma unroll
            for (int ni = 0; ni < 4; ni++) {
                wmma::fragment<wmma::matrix_b, 16, 16, 16, __nv_bfloat16, wmma::row_major> bfr;
                wmma::load_matrix_sync(bfr, &Bs[ks * 16][warpN0 + ni * 16], 136);
                wmma::mma_sync(cf[0][ni], af[0], bfr, cf[0][ni]);
                wmma::mma_sync(cf[1][ni], af[1], bfr, cf[1][ni]);
            }
        }
        __syncthreads();
    }
    // epilogue: frag -> Cbuf -> bias + el/er + bf16 pack
    int halfc = lane & 1;    // 8-col half within 16-col frag
    int rl = lane >> 1;      // row within frag
#pragma unroll
    for (int mi = 0; mi < 2; mi++) {
        int gm = m0 + warpM0 + mi * 16 + rl;
        float el = 0.f, er = 0.f;
#pragma unroll
        for (int ni = 0; ni < 4; ni++) {
            wmma::store_matrix_sync(&Cbuf[w][0][0], cf[mi][ni], 20, wmma::mem_row_major);
            __syncwarp();
            int cin = ni * 16 + halfc * 8;   // col within head
            float4 bb0 = *(const float4*)(B1 + hd * 64 + cin);
            float4 bb1 = *(const float4*)(B1 + hd * 64 + cin + 4);
            float4 ad0 = *(const float4*)(A1 + hd * 128 + cin);
            float4 ad1 = *(const float4*)(A1 + hd * 128 + cin + 4);
            float4 as0 = *(const float4*)(A1 + hd * 128 + 64 + cin);
            float4 as1 = *(const float4*)(A1 + hd * 128 + 64 + cin + 4);
            const float* cr = &Cbuf[w][rl][halfc * 8];
            float v0 = cr[0] + bb0.x, v1 = cr[1] + bb0.y;
            float v2 = cr[2] + bb0.z, v3 = cr[3] + bb0.w;
            float v4 = cr[4] + bb1.x, v5 = cr[5] + bb1.y;
            float v6 = cr[6] + bb1.z, v7 = cr[7] + bb1.w;
            el += v0 * ad0.x + v1 * ad0.y + v2 * ad0.z + v3 * ad0.w
                + v4 * ad1.x + v5 * ad1.y + v6 * ad1.z + v7 * ad1.w;
            er += v0 * as0.x + v1 * as0.y + v2 * as0.z + v3 * as0.w
                + v4 * as1.x + v5 * as1.y + v6 * as1.z + v7 * as1.w;
            if (gm < NN) {
                uint4 pk;
                pk.x = pack_bf2(v0, v1);
                pk.y = pack_bf2(v2, v3);
                pk.z = pack_bf2(v4, v5);
                pk.w = pack_bf2(v6, v7);
                *(uint4*)&d_Wh1b[(size_t)gm * C1 + hd * 64 + cin] = pk;
            }
            __syncwarp();
        }
        el += __shfl_xor_sync(0xffffffffu, el, 1);
        er += __shfl_xor_sync(0xffffffffu, er, 1);
        if (halfc == 0 && gm < NN) {
            d_el1[gm * 4 + hd] = el;
            d_er1[gm * 4 + hd] = er;
        }
    }
}

// ---------------- layer-1 segment softmax + aggregation (warp per dst node) ------
__global__ __launch_bounds__(256) void k_agg1(const float* __restrict__ ab1) {
    int w = (blockIdx.x * blockDim.x + threadIdx.x) >> 5;
    int lane = threadIdx.x & 31;
    if (w >= NN) return;
    int n = w;
    int start = d_rowstart[n], deg = d_deg[n];
    if (deg == 0) {
        *(uint4*)&d_h1b[(size_t)n * C1 + lane * 8] = make_uint4(0, 0, 0, 0);
        return;
    }
    float4 el = *(const float4*)(d_el1 + n * 4);
    float4 ab = make_float4(ab1[0], ab1[1], ab1[2], ab1[3]);
    float4 elb = f4add(el, ab);
    // phase 1: max
    float4 mx = f4make(-INFINITY);
    for (int i = lane; i < deg; i += 32) {
        int s = d_csr[start + i];
        float4 er = *(const float4*)(d_er1 + s * 4);
        mx = f4max(mx, f4leaky(f4add(elb, er)));
    }
#pragma unroll
    for (int off = 16; off; off >>= 1) {
        mx.x = fmaxf(mx.x, __shfl_xor_sync(0xffffffffu, mx.x, off));
        mx.y = fmaxf(mx.y, __shfl_xor_sync(0xffffffffu, mx.y, off));
        mx.z = fmaxf(mx.z, __shfl_xor_sync(0xffffffffu, mx.z, off));
        mx.w = fmaxf(mx.w, __shfl_xor_sync(0xffffffffu, mx.w, off));
    }
    // phase 2: sum of exp
    float4 se = f4make(0.f);
    for (int i = lane; i < deg; i += 32) {
        int s = d_csr[start + i];
        float4 er = *(const float4*)(d_er1 + s * 4);
        float4 e = f4leaky(f4add(elb, er));
        se = f4add(se, f4expsub(e, mx));
    }
#pragma unroll
    for (int off = 16; off; off >>= 1) {
        se.x += __shfl_xor_sync(0xffffffffu, se.x, off);
        se.y += __shfl_xor_sync(0xffffffffu, se.y, off);
        se.z += __shfl_xor_sync(0xffffffffu, se.z, off);
        se.w += __shfl_xor_sync(0xffffffffu, se.w, off);
    }
    // phase 3: lane owns 8 contiguous bf16 cols lane*8..+7; head = lane>>3
    int h = lane >> 3;
    float mh = pick4(mx, h);
    float ih = 1.f / pick4(se, h);
    float ebh = pick4(elb, h);
    float acc[8] = {};
    const int* cp = d_csr + start;
    for (int i = 0; i < deg; i++) {
        int s = cp[i];
        float4 er = *(const float4*)(d_er1 + s * 4);
        float e = ebh + pick4(er, h);
        e = fmaxf(e, 0.2f * e);
        float al = __expf(e - mh) * ih;
        uint4 raw = *(const uint4*)&d_Wh1b[(size_t)s * C1 + lane * 8];
        float2 f0 = __bfloat1622float2(*reinterpret_cast<__nv_bfloat162*>(&raw.x));
        float2 f1 = __bfloat1622float2(*reinterpret_cast<__nv_bfloat162*>(&raw.y));
        float2 f2 = __bfloat1622float2(*reinterpret_cast<__nv_bfloat162*>(&raw.z));
        float2 f3 = __bfloat1622float2(*reinterpret_cast<__nv_bfloat162*>(&raw.w));
        acc[0] = fmaf(al, f0.x, acc[0]); acc[1] = fmaf(al, f0.y, acc[1]);
        acc[2] = fmaf(al, f1.x, acc[2]); acc[3] = fmaf(al, f1.y, acc[3]);
        acc[4] = fmaf(al, f2.x, acc[4]); acc[5] = fmaf(al, f2.y, acc[5]);
        acc[6] = fmaf(al, f3.x, acc[6]); acc[7] = fmaf(al, f3.y, acc[7]);
    }
    // fused ELU + bf16 pack
    uint4 po;
    po.x = pack_bf2(eluf(acc[0]), eluf(acc[1]));
    po.y = pack_bf2(eluf(acc[2]), eluf(acc[3]));
    po.z = pack_bf2(eluf(acc[4]), eluf(acc[5]));
    po.w = pack_bf2(eluf(acc[6]), eluf(acc[7]));
    *(uint4*)&d_h1b[(size_t)n * C1 + lane * 8] = po;
}

// ---- GEMM2: [NN,256]bf16 @ [256,64], 128-row tile, 8x8 microtile, f32x2 ----
__global__ __launch_bounds__(128) void k_gemm2(const float* __restrict__ W2,
                                               const float* __restrict__ B2,
                                               const float* __restrict__ A2) {
    __shared__ __align__(16) float As[32][128];
    __shared__ __align__(16) float Bs[32][64];
    int m0 = blockIdx.x * 128;
    int tid = threadIdx.x;
    int tx = tid & 7, ty = tid >> 3;
    unsigned long long acc[8][4];
#pragma unroll
    for (int i = 0; i < 8; i++)
#pragma unroll
        for (int j = 0; j < 4; j++) acc[i][j] = 0ull;

    for (int kc = 0; kc < 256; kc += 32) {
        // stage A from bf16 h1: thread = row, t = k-octet
        {
            int gm = m0 + tid;
            bool ok = gm < NN;
#pragma unroll
            for (int t = 0; t < 4; t++) {
                uint4 raw = ok ? *(const uint4*)&d_h1b[(size_t)gm * C1 + kc + t * 8]
                               : make_uint4(0, 0, 0, 0);
                float2 f0 = __bfloat1622float2(*reinterpret_cast<__nv_bfloat162*>(&raw.x));
                float2 f1 = __bfloat1622float2(*reinterpret_cast<__nv_bfloat162*>(&raw.y));
                float2 f2 = __bfloat1622float2(*reinterpret_cast<__nv_bfloat162*>(&raw.z));
                float2 f3 = __bfloat1622float2(*reinterpret_cast<__nv_bfloat162*>(&raw.w));
                As[t * 8 + 0][tid] = f0.x; As[t * 8 + 1][tid] = f0.y;
                As[t * 8 + 2][tid] = f1.x; As[t * 8 + 3][tid] = f1.y;
                As[t * 8 + 4][tid] = f2.x; As[t * 8 + 5][tid] = f2.y;
                As[t * 8 + 6][tid] = f3.x; As[t * 8 + 7][tid] = f3.y;
            }
        }
        // stage B
#pragma unroll
        for (int t = 0; t < 4; t++) {
            int i = tid + t * 128;
            int k = i >> 4, c4 = (i & 15) * 4;
            int hh = c4 >> 4, oo = c4 & 15;
            *(float4*)&Bs[k][c4] =
                *(const float4*)(W2 + (size_t)hh * 4096 + (size_t)(kc + k) * 16 + oo);
        }
        __syncthreads();
#pragma unroll 8
        for (int k = 0; k < 32; k++) {
            float4 av0 = *(const float4*)&As[k][ty * 8];
            float4 av1 = *(const float4*)&As[k][ty * 8 + 4];
            ulonglong2 bA = *(const ulonglong2*)&Bs[k][tx * 4];
            ulonglong2 bB = *(const ulonglong2*)&Bs[k][32 + tx * 4];
            float aa[8] = {av0.x, av0.y, av0.z, av0.w, av1.x, av1.y, av1.z, av1.w};
#pragma unroll
            for (int i = 0; i < 8; i++) {
                unsigned long long a2v;
                SPLAT2(a2v, aa[i]);
                FMA2(acc[i][0], a2v, bA.x);
                FMA2(acc[i][1], a2v, bA.y);
                FMA2(acc[i][2], a2v, bB.x);
                FMA2(acc[i][3], a2v, bB.y);
            }
        }
        __syncthreads();
    }
    // epilogue: group0 cols tx*4 (head tx>>2), group1 cols 32+tx*4 (head 2+(tx>>2))
    int hA = tx >> 2, hB = 2 + (tx >> 2);
    int o = (tx & 3) * 4;
    float4 bbA = *(const float4*)(B2 + hA * 16 + o);
    float4 bbB = *(const float4*)(B2 + hB * 16 + o);
    float4 adA = *(const float4*)(A2 + hA * 32 + o);
    float4 asA = *(const float4*)(A2 + hA * 32 + 16 + o);
    float4 adB = *(const float4*)(A2 + hB * 32 + o);
    float4 asB = *(const float4*)(A2 + hB * 32 + 16 + o);
#pragma unroll
    for (int i = 0; i < 8; i++) {
        int gm = m0 + ty * 8 + i;
        float o00 = lo64(acc[i][0]) + bbA.x, o01 = hi64(acc[i][0]) + bbA.y;
        float o02 = lo64(acc[i][1]) + bbA.z, o03 = hi64(acc[i][1]) + bbA.w;
        float o10 = lo64(acc[i][2]) + bbB.x, o11 = hi64(acc[i][2]) + bbB.y;
        float o12 = lo64(acc[i][3]) + bbB.z, o13 = hi64(acc[i][3]) + bbB.w;
        float pElA = o00 * adA.x + o01 * adA.y + o02 * adA.z + o03 * adA.w;
        float pErA = o00 * asA.x + o01 * asA.y + o02 * asA.z + o03 * asA.w;
        float pElB = o10 * adB.x + o11 * adB.y + o12 * adB.z + o13 * adB.w;
        float pErB = o10 * asB.x + o11 * asB.y + o12 * asB.z + o13 * asB.w;
#pragma unroll
        for (int off = 2; off; off >>= 1) {
            pElA += __shfl_xor_sync(0xffffffffu, pElA, off);
            pErA += __shfl_xor_sync(0xffffffffu, pErA, off);
            pElB += __shfl_xor_sync(0xffffffffu, pElB, off);
            pErB += __shfl_xor_sync(0xffffffffu, pErB, off);
        }
        if (gm < NN) {
            *(uint2*)&d_Wh2b[(size_t)gm * C2 + tx * 4] =
                make_uint2(pack_bf2(o00, o01), pack_bf2(o02, o03));
            *(uint2*)&d_Wh2b[(size_t)gm * C2 + 32 + tx * 4] =
                make_uint2(pack_bf2(o10, o11), pack_bf2(o12, o13));
            if ((tx & 3) == 0) {
                d_el2[gm * 4 + hA] = pElA;
                d_er2[gm * 4 + hA] = pErA;
                d_el2[gm * 4 + hB] = pElB;
                d_er2[gm * 4 + hB] = pErB;
            }
        }
    }
}

// ---------------- layer-2 segment softmax + aggregation ----------------
__global__ __launch_bounds__(256) void k_agg2(const float* __restrict__ ab2) {
    int w = (blockIdx.x * blockDim.x + threadIdx.x) >> 5;
    int lane = threadIdx.x & 31;
    if (w >= NN) return;
    int n = w;
    int start = d_rowstart[n], deg = d_deg[n];
    float2* outp = (float2*)(d_out2 + (size_t)n * C2);
    if (deg == 0) {
        outp[lane] = make_float2(0.f, 0.f);
        return;
    }
    float4 el = *(const float4*)(d_el2 + n * 4);
    float4 ab = make_float4(ab2[0], ab2[1], ab2[2], ab2[3]);
    float4 elb = f4add(el, ab);
    float4 mx = f4make(-INFINITY);
    for (int i = lane; i < deg; i += 32) {
        int s = d_csr[start + i];
        float4 er = *(const float4*)(d_er2 + s * 4);
        mx = f4max(mx, f4leaky(f4add(elb, er)));
    }
#pragma unroll
    for (int off = 16; off; off >>= 1) {
        mx.x = fmaxf(mx.x, __shfl_xor_sync(0xffffffffu, mx.x, off));
        mx.y = fmaxf(mx.y, __shfl_xor_sync(0xffffffffu, mx.y, off));
        mx.z = fmaxf(mx.z, __shfl_xor_sync(0xffffffffu, mx.z, off));
        mx.w = fmaxf(mx.w, __shfl_xor_sync(0xffffffffu, mx.w, off));
    }
    float4 se = f4make(0.f);
    for (int i = lane; i < deg; i += 32) {
        int s = d_csr[start + i];
        float4 er = *(const float4*)(d_er2 + s * 4);
        float4 e = f4leaky(f4add(elb, er));
        se = f4add(se, f4expsub(e, mx));
    }
#pragma unroll
    for (int off = 16; off; off >>= 1) {
        se.x += __shfl_xor_sync(0xffffffffu, se.x, off);
        se.y += __shfl_xor_sync(0xffffffffu, se.y, off);
        se.z += __shfl_xor_sync(0xffffffffu, se.z, off);
        se.w += __shfl_xor_sync(0xffffffffu, se.w, off);
    }
    int h = lane >> 3;
    float mh = pick4(mx, h);
    float ih = 1.f / pick4(se, h);
    float ebh = pick4(elb, h);
    float2 acc = make_float2(0.f, 0.f);
    const int* cp = d_csr + start;
    for (int i = 0; i < deg; i++) {
        int s = cp[i];
        float4 er = *(const float4*)(d_er2 + s * 4);
        float e = ebh + pick4(er, h);
        e = fmaxf(e, 0.2f * e);
        float al = __expf(e - mh) * ih;
        __nv_bfloat162 wv = *(const __nv_bfloat162*)&d_Wh2b[(size_t)s * C2 + lane * 2];
        float2 wf = __bfloat1622float2(wv);
        acc.x = fmaf(al, wf.x, acc.x);
        acc.y = fmaf(al, wf.y, acc.y);
    }
    outp[lane] = acc;
}

// ---------------- readout: head-mean -> softmax -> node-mean ----------------
__global__ void k_final() {
    __shared__ float ssum[NCLS];
    if (threadIdx.x < NCLS) ssum[threadIdx.x] = 0.f;
    __syncthreads();
    float loc[NCLS];
#pragma unroll
    for (int k = 0; k < NCLS; k++) loc[k] = 0.f;
    for (int n = blockIdx.x * blockDim.x + threadIdx.x; n < NN;
         n += gridDim.x * blockDim.x) {
        const float* row = d_out2 + (size_t)n * C2;
        float z[NCLS];
#pragma unroll
        for (int k = 0; k < NCLS; k++)
            z[k] = 0.25f * (row[k] + row[16 + k] + row[32 + k] + row[48 + k]);
        float mx = z[0];
#pragma unroll
        for (int k = 1; k < NCLS; k++) mx = fmaxf(mx, z[k]);
        float s = 0.f;
#pragma unroll
        for (int k = 0; k < NCLS; k++) {
            z[k] = __expf(z[k] - mx);
            s += z[k];
        }
        float invs = 1.f / s;
#pragma unroll
        for (int k = 0; k < NCLS; k++) loc[k] += z[k] * invs;
    }
#pragma unroll
    for (int k = 0; k < NCLS; k++) atomicAdd(&ssum[k], loc[k]);
    __syncthreads();
    if (threadIdx.x < NCLS) atomicAdd(&d_cls[threadIdx.x], ssum[threadIdx.x]);
}

__global__ void k_fc(const float* __restrict__ fcw, const float* __restrict__ fcb,
                     float* __restrict__ out) {
    int c = threadIdx.x;
    if (c < NCLS) {
        float s = fcb[c];
        const float scale = 1.f / (float)NN;
#pragma unroll
        for (int k = 0; k < NCLS; k++) s = fmaf(d_cls[k] * scale, fcw[c * NCLS + k], s);
        out[c] = s;
    }
}

// ---------------- launch ----------------
extern "C" void kernel_launch(void* const* d_in, const int* in_sizes, int n_in,
                              void* d_out, int out_size) {
    const float* h   = (const float*)d_in[0];
    const int*   src = (const int*)d_in[1];
    const int*   dst = (const int*)d_in[2];
    const float* W1  = (const float*)d_in[3];
    const float* b1  = (const float*)d_in[4];
    const float* a1  = (const float*)d_in[5];
    const float* ab1 = (const float*)d_in[6];
    const float* W2  = (const float*)d_in[7];
    const float* b2  = (const float*)d_in[8];
    const float* a2  = (const float*)d_in[9];
    const float* ab2 = (const float*)d_in[10];
    const float* fcw = (const float*)d_in[11];
    const float* fcb = (const float*)d_in[12];
    float* out = (float*)d_out;

    k_init<<<(NN + 255) / 256, 256>>>();                           // 0
    k_hist<<<(NE + 255) / 256, 256>>>(dst);                        // 1
    k_chunkred<<<NCH, 256>>>();                                    // 2
    k_gemm1<<<dim3((NN + 127) / 128, 2), 256>>>(h, W1, b1, a1);    // 3 (ncu slot)
    k_scanlocal<<<NCH, 256>>>();                                   // 4
    k_scatter<<<(NE + 255) / 256, 256>>>(src, dst);                // 5
    k_agg1<<<(NN * 32 + 255) / 256, 256>>>(ab1);                   // 6
    k_gemm2<<<(NN + 127) / 128, 128>>>(W2, b2, a2);                // 7
    k_agg2<<<(NN * 32 + 255) / 256, 256>>>(ab2);                   // 8
    k_final<<<400, 256>>>();                                       // 9
    k_fc<<<1, 32>>>(fcw, fcb, out);                                // 10
}